// round 4
// baseline (speedup 1.0000x reference)
#include <cuda_runtime.h>
#include <math.h>

// ---------------------------------------------------------------------------
// Problem constants (fixed shapes from the reference)
// ---------------------------------------------------------------------------
#define Bc    8
#define Sc    2048
#define DMc   1024
#define DKc   512
#define DVc   512
#define DOUTc 1024
#define NTc   (Bc * Sc)              // 16384 tokens

static const long OFF_OUT = 0L;                                  // (B,S,DOUT)
static const long OFF_RES = (long)NTc * DOUTc;                   // 16777216
static const long OFF_ATT = OFF_RES + (long)NTc * DKc;           // 25165824

#define INV_TEMP 0.04419417382415922f   // 1/sqrt(512)

// ---------------------------------------------------------------------------
// Scratch (static device globals — no allocation at runtime).
// Buffer lifetimes allow aliasing:
//   g_qp: LN'd q  ......... dead after scores GEMM -> reused for out1 (attn@V)
//   g_kp: LN'd k  ......... dead after scores GEMM -> reused for MLP hidden
//   g_vp: LN'd v  ......... live through attn@V
// ---------------------------------------------------------------------------
__device__ __align__(16) float g_qp[(size_t)NTc * DKc];
__device__ __align__(16) float g_kp[(size_t)NTc * DKc];
__device__ __align__(16) float g_vp[(size_t)NTc * DVc];

// ---------------------------------------------------------------------------
// Tiled SGEMM: C = alpha * A @ B (+bias) (+relu), optional batched via grid.z
//   A: row-major [M,K], lda = K
//   B: TRANSB ? row-major [N,K] (ldb=K, computes A@B^T) : row-major [K,N] (ldb=N)
//   C: row-major [M,N], ldc = N
// BM=BN=128, BK=16, 256 threads, 8x8 per-thread microtile.
// Double-buffered smem, register-staged global prefetch, 1 barrier per K-tile.
// All of M,N multiples of 128; K multiple of 16; pointers 16B-aligned.
// ---------------------------------------------------------------------------
#define BM 128
#define BN 128
#define BK 16

template<bool TRANSB, bool BIAS, bool RELU>
__global__ __launch_bounds__(256)
void sgemm_kernel(const float* __restrict__ A, const float* __restrict__ Bm,
                  const float* __restrict__ bias, float* __restrict__ C,
                  int M, int N, int K,
                  long sA, long sB, long sC, float alpha)
{
    A  += (long)blockIdx.z * sA;
    Bm += (long)blockIdx.z * sB;
    C  += (long)blockIdx.z * sC;

    __shared__ float As[2][BK][BM];
    __shared__ float Bs[2][BK][BN];

    const int tid = threadIdx.x;
    const int tx  = tid & 15;     // 0..15 -> N direction
    const int ty  = tid >> 4;     // 0..15 -> M direction
    const int m0  = blockIdx.y * BM;
    const int n0  = blockIdx.x * BN;

    // load-index precompute
    const int aRow = tid >> 2;            // 0..63 (second chunk: +64)
    const int aK4  = (tid & 3) << 2;      // 0,4,8,12
    const int bRow = tid >> 5;            // 0..7  (second chunk: +8)   [!TRANSB]
    const int bC4  = (tid & 31) << 2;     // 0..124                     [!TRANSB]

    float acc[8][8];
#pragma unroll
    for (int i = 0; i < 8; i++)
#pragma unroll
        for (int j = 0; j < 8; j++) acc[i][j] = 0.f;

    float4 aV0, aV1, bV0, bV1;

    // ---- prologue: load tile 0 into registers
    aV0 = *reinterpret_cast<const float4*>(A + (long)(m0 + aRow)      * K + aK4);
    aV1 = *reinterpret_cast<const float4*>(A + (long)(m0 + aRow + 64) * K + aK4);
    if (TRANSB) {
        bV0 = *reinterpret_cast<const float4*>(Bm + (long)(n0 + aRow)      * K + aK4);
        bV1 = *reinterpret_cast<const float4*>(Bm + (long)(n0 + aRow + 64) * K + aK4);
    } else {
        bV0 = *reinterpret_cast<const float4*>(Bm + (long)(bRow)     * N + n0 + bC4);
        bV1 = *reinterpret_cast<const float4*>(Bm + (long)(bRow + 8) * N + n0 + bC4);
    }
    // store tile 0 -> buffer 0
    As[0][aK4 + 0][aRow] = aV0.x; As[0][aK4 + 1][aRow] = aV0.y;
    As[0][aK4 + 2][aRow] = aV0.z; As[0][aK4 + 3][aRow] = aV0.w;
    As[0][aK4 + 0][aRow + 64] = aV1.x; As[0][aK4 + 1][aRow + 64] = aV1.y;
    As[0][aK4 + 2][aRow + 64] = aV1.z; As[0][aK4 + 3][aRow + 64] = aV1.w;
    if (TRANSB) {
        Bs[0][aK4 + 0][aRow] = bV0.x; Bs[0][aK4 + 1][aRow] = bV0.y;
        Bs[0][aK4 + 2][aRow] = bV0.z; Bs[0][aK4 + 3][aRow] = bV0.w;
        Bs[0][aK4 + 0][aRow + 64] = bV1.x; Bs[0][aK4 + 1][aRow + 64] = bV1.y;
        Bs[0][aK4 + 2][aRow + 64] = bV1.z; Bs[0][aK4 + 3][aRow + 64] = bV1.w;
    } else {
        *reinterpret_cast<float4*>(&Bs[0][bRow][bC4])     = bV0;
        *reinterpret_cast<float4*>(&Bs[0][bRow + 8][bC4]) = bV1;
    }
    __syncthreads();

    const int T = K / BK;
    for (int it = 0; it < T; it++) {
        const int cur = it & 1;
        const int k0n = (it + 1) * BK;

        // ---- prefetch next tile into registers (overlaps with compute below)
        if (it + 1 < T) {
            aV0 = *reinterpret_cast<const float4*>(A + (long)(m0 + aRow)      * K + k0n + aK4);
            aV1 = *reinterpret_cast<const float4*>(A + (long)(m0 + aRow + 64) * K + k0n + aK4);
            if (TRANSB) {
                bV0 = *reinterpret_cast<const float4*>(Bm + (long)(n0 + aRow)      * K + k0n + aK4);
                bV1 = *reinterpret_cast<const float4*>(Bm + (long)(n0 + aRow + 64) * K + k0n + aK4);
            } else {
                bV0 = *reinterpret_cast<const float4*>(Bm + (long)(k0n + bRow)     * N + n0 + bC4);
                bV1 = *reinterpret_cast<const float4*>(Bm + (long)(k0n + bRow + 8) * N + n0 + bC4);
            }
        }

        // ---- compute on current buffer
#pragma unroll
        for (int kk = 0; kk < BK; kk++) {
            float a[8], b[8];
            *reinterpret_cast<float4*>(a)     = *reinterpret_cast<const float4*>(&As[cur][kk][ty * 8]);
            *reinterpret_cast<float4*>(a + 4) = *reinterpret_cast<const float4*>(&As[cur][kk][ty * 8 + 4]);
            *reinterpret_cast<float4*>(b)     = *reinterpret_cast<const float4*>(&Bs[cur][kk][tx * 8]);
            *reinterpret_cast<float4*>(b + 4) = *reinterpret_cast<const float4*>(&Bs[cur][kk][tx * 8 + 4]);
#pragma unroll
            for (int i = 0; i < 8; i++)
#pragma unroll
                for (int j = 0; j < 8; j++)
                    acc[i][j] += a[i] * b[j];
        }

        // ---- store prefetched tile into the other buffer, single barrier
        if (it + 1 < T) {
            const int nxt = cur ^ 1;
            As[nxt][aK4 + 0][aRow] = aV0.x; As[nxt][aK4 + 1][aRow] = aV0.y;
            As[nxt][aK4 + 2][aRow] = aV0.z; As[nxt][aK4 + 3][aRow] = aV0.w;
            As[nxt][aK4 + 0][aRow + 64] = aV1.x; As[nxt][aK4 + 1][aRow + 64] = aV1.y;
            As[nxt][aK4 + 2][aRow + 64] = aV1.z; As[nxt][aK4 + 3][aRow + 64] = aV1.w;
            if (TRANSB) {
                Bs[nxt][aK4 + 0][aRow] = bV0.x; Bs[nxt][aK4 + 1][aRow] = bV0.y;
                Bs[nxt][aK4 + 2][aRow] = bV0.z; Bs[nxt][aK4 + 3][aRow] = bV0.w;
                Bs[nxt][aK4 + 0][aRow + 64] = bV1.x; Bs[nxt][aK4 + 1][aRow + 64] = bV1.y;
                Bs[nxt][aK4 + 2][aRow + 64] = bV1.z; Bs[nxt][aK4 + 3][aRow + 64] = bV1.w;
            } else {
                *reinterpret_cast<float4*>(&Bs[nxt][bRow][bC4])     = bV0;
                *reinterpret_cast<float4*>(&Bs[nxt][bRow + 8][bC4]) = bV1;
            }
            __syncthreads();
        }
    }

    // ---- epilogue
    const int nbase = n0 + tx * 8;
    float4 bs0, bs1;
    if (BIAS) {
        bs0 = *reinterpret_cast<const float4*>(bias + nbase);
        bs1 = *reinterpret_cast<const float4*>(bias + nbase + 4);
    }
#pragma unroll
    for (int i = 0; i < 8; i++) {
        long m = m0 + ty * 8 + i;
        float4 r0, r1;
        r0.x = acc[i][0] * alpha; r0.y = acc[i][1] * alpha;
        r0.z = acc[i][2] * alpha; r0.w = acc[i][3] * alpha;
        r1.x = acc[i][4] * alpha; r1.y = acc[i][5] * alpha;
        r1.z = acc[i][6] * alpha; r1.w = acc[i][7] * alpha;
        if (BIAS) {
            r0.x += bs0.x; r0.y += bs0.y; r0.z += bs0.z; r0.w += bs0.w;
            r1.x += bs1.x; r1.y += bs1.y; r1.z += bs1.z; r1.w += bs1.w;
        }
        if (RELU) {
            r0.x = fmaxf(r0.x, 0.f); r0.y = fmaxf(r0.y, 0.f);
            r0.z = fmaxf(r0.z, 0.f); r0.w = fmaxf(r0.w, 0.f);
            r1.x = fmaxf(r1.x, 0.f); r1.y = fmaxf(r1.y, 0.f);
            r1.z = fmaxf(r1.z, 0.f); r1.w = fmaxf(r1.w, 0.f);
        }
        *reinterpret_cast<float4*>(C + m * (long)N + nbase)     = r0;
        *reinterpret_cast<float4*>(C + m * (long)N + nbase + 4) = r1;
    }
}

// ---------------------------------------------------------------------------
// LayerNorm over last dim D=512, eps=1e-6, affine. 128 threads, 1 row/block.
// Optionally copies the raw (pre-LN) row to `res` (the residual output).
// In-place safe (reads into registers first).
// ---------------------------------------------------------------------------
__global__ __launch_bounds__(128)
void ln512_kernel(const float* __restrict__ X,
                  const float* __restrict__ gam, const float* __restrict__ bet,
                  float* __restrict__ Y, float* __restrict__ res)
{
    long row = blockIdx.x;
    const int t = threadIdx.x;
    float4 v = reinterpret_cast<const float4*>(X + row * 512)[t];

    float s  = v.x + v.y + v.z + v.w;
    float sq = v.x * v.x + v.y * v.y + v.z * v.z + v.w * v.w;
#pragma unroll
    for (int o = 16; o > 0; o >>= 1) {
        s  += __shfl_xor_sync(0xffffffffu, s, o);
        sq += __shfl_xor_sync(0xffffffffu, sq, o);
    }
    __shared__ float sh_s[4], sh_q[4];
    int w = t >> 5, l = t & 31;
    if (l == 0) { sh_s[w] = s; sh_q[w] = sq; }
    __syncthreads();
    s  = sh_s[0] + sh_s[1] + sh_s[2] + sh_s[3];
    sq = sh_q[0] + sh_q[1] + sh_q[2] + sh_q[3];

    float mean = s * (1.f / 512.f);
    float var  = sq * (1.f / 512.f) - mean * mean;
    float rs   = rsqrtf(var + 1e-6f);

    if (res) reinterpret_cast<float4*>(res + row * 512)[t] = v;

    float4 g4 = reinterpret_cast<const float4*>(gam)[t];
    float4 b4 = reinterpret_cast<const float4*>(bet)[t];
    float4 o;
    o.x = (v.x - mean) * rs * g4.x + b4.x;
    o.y = (v.y - mean) * rs * g4.y + b4.y;
    o.z = (v.z - mean) * rs * g4.z + b4.z;
    o.w = (v.w - mean) * rs * g4.w + b4.w;
    reinterpret_cast<float4*>(Y + row * 512)[t] = o;
}

// ---------------------------------------------------------------------------
// Mask + softmax over rows of 2048, in place. 256 threads, 8 elems/thread.
// Row r = b*S + q; mask layout (B,S,S) matches scores layout flat.
// ---------------------------------------------------------------------------
__global__ __launch_bounds__(256)
void softmax2048_kernel(float* __restrict__ Scores, const int* __restrict__ mask)
{
    long row = blockIdx.x;
    float* s      = Scores + row * 2048;
    const int* m  = mask   + row * 2048;
    const int t = threadIdx.x;

    float vals[8];
    float mx = -1e30f;
#pragma unroll
    for (int i = 0; i < 8; i++) {
        int c = t + i * 256;
        float x = s[c];
        if (m[c] == 0) x = -1e9f;
        vals[i] = x;
        mx = fmaxf(mx, x);
    }
    __shared__ float sh[8];
#pragma unroll
    for (int o = 16; o > 0; o >>= 1) mx = fmaxf(mx, __shfl_xor_sync(0xffffffffu, mx, o));
    int w = t >> 5, l = t & 31;
    if (l == 0) sh[w] = mx;
    __syncthreads();
    mx = sh[0];
#pragma unroll
    for (int i = 1; i < 8; i++) mx = fmaxf(mx, sh[i]);
    __syncthreads();

    float sum = 0.f;
#pragma unroll
    for (int i = 0; i < 8; i++) {
        vals[i] = __expf(vals[i] - mx);
        sum += vals[i];
    }
#pragma unroll
    for (int o = 16; o > 0; o >>= 1) sum += __shfl_xor_sync(0xffffffffu, sum, o);
    if (l == 0) sh[w] = sum;
    __syncthreads();
    sum = sh[0] + sh[1] + sh[2] + sh[3] + sh[4] + sh[5] + sh[6] + sh[7];

    float inv = 1.f / sum;
#pragma unroll
    for (int i = 0; i < 8; i++) s[t + i * 256] = vals[i] * inv;
}

// ---------------------------------------------------------------------------
// Launch
// ---------------------------------------------------------------------------
extern "C" void kernel_launch(void* const* d_in, const int* in_sizes, int n_in,
                              void* d_out_, int out_size)
{
    const float* q    = (const float*)d_in[0];
    const float* k    = (const float*)d_in[1];
    const float* v    = (const float*)d_in[2];
    const int*   mask = (const int*)  d_in[3];
    const float* Wq   = (const float*)d_in[4];
    const float* bq   = (const float*)d_in[5];
    const float* Wk   = (const float*)d_in[6];
    const float* bk   = (const float*)d_in[7];
    const float* Wv   = (const float*)d_in[8];
    const float* bv   = (const float*)d_in[9];
    const float* gq   = (const float*)d_in[10];
    const float* beq  = (const float*)d_in[11];
    const float* gk   = (const float*)d_in[12];
    const float* bek  = (const float*)d_in[13];
    const float* gv   = (const float*)d_in[14];
    const float* bev  = (const float*)d_in[15];
    const float* W1   = (const float*)d_in[16];
    const float* b1   = (const float*)d_in[17];
    const float* W2   = (const float*)d_in[18];
    const float* b2   = (const float*)d_in[19];
    float* out = (float*)d_out_;

    float *qp, *kp, *vp;
    cudaGetSymbolAddress((void**)&qp, g_qp);
    cudaGetSymbolAddress((void**)&kp, g_kp);
    cudaGetSymbolAddress((void**)&vp, g_vp);
    float* t1 = qp;   // out1 (attn @ V)   — qp dead after scores GEMM
    float* t2 = kp;   // MLP hidden        — kp dead after scores GEMM

    dim3 blk(256);

    // 1-3) QKV projections (+bias): [16384,1024] @ [1024,512]
    {
        dim3 grid(DKc / BN, NTc / BM, 1);
        sgemm_kernel<false, true, false><<<grid, blk>>>(q, Wq, bq, qp, NTc, DKc, DMc, 0, 0, 0, 1.f);
        sgemm_kernel<false, true, false><<<grid, blk>>>(k, Wk, bk, kp, NTc, DKc, DMc, 0, 0, 0, 1.f);
        sgemm_kernel<false, true, false><<<grid, blk>>>(v, Wv, bv, vp, NTc, DVc, DMc, 0, 0, 0, 1.f);
    }

    // 4-6) LayerNorm (in place). q-LN also emits residual = raw qp.
    ln512_kernel<<<NTc, 128>>>(qp, gq, beq, qp, out + OFF_RES);
    ln512_kernel<<<NTc, 128>>>(kp, gk, bek, kp, nullptr);
    ln512_kernel<<<NTc, 128>>>(vp, gv, bev, vp, nullptr);

    // 7) scores = (qn/sqrt(dk)) @ kn^T, batched over B; write into attn region
    {
        dim3 grid(Sc / BN, Sc / BM, Bc);
        sgemm_kernel<true, false, false><<<grid, blk>>>(
            qp, kp, nullptr, out + OFF_ATT,
            Sc, Sc, DKc,
            (long)Sc * DKc, (long)Sc * DKc, (long)Sc * Sc, INV_TEMP);
    }

    // 8) mask + softmax, in place in attn region
    softmax2048_kernel<<<NTc, 256>>>(out + OFF_ATT, mask);

    // 9) out1 = attn @ vn, batched over B  (into t1 == qp, now dead)
    {
        dim3 grid(DVc / BN, Sc / BM, Bc);
        sgemm_kernel<false, false, false><<<grid, blk>>>(
            out + OFF_ATT, vp, nullptr, t1,
            Sc, DVc, Sc,
            (long)Sc * Sc, (long)Sc * DVc, (long)Sc * DVc, 1.f);
    }

    // 10) h = relu(out1 @ W1 + b1)  (into t2 == kp, now dead)
    {
        dim3 grid(DVc / BN, NTc / BM, 1);
        sgemm_kernel<false, true, true><<<grid, blk>>>(t1, W1, b1, t2, NTc, DVc, DVc, 0, 0, 0, 1.f);
    }

    // 11) out = h @ W2 + b2
    {
        dim3 grid(DOUTc / BN, NTc / BM, 1);
        sgemm_kernel<false, true, false><<<grid, blk>>>(t2, W2, b2, out + OFF_OUT, NTc, DOUTc, DVc, 0, 0, 0, 1.f);
    }
}

// round 6
// speedup vs baseline: 2.5805x; 2.5805x over previous
#include <cuda_runtime.h>
#include <math.h>
#include <stdint.h>

// ---------------------------------------------------------------------------
// Problem constants
// ---------------------------------------------------------------------------
#define Bc    8
#define Sc    2048
#define DMc   1024
#define DKc   512
#define DVc   512
#define DOUTc 1024
#define NTc   (Bc * Sc)              // 16384 tokens

static const long OFF_OUT = 0L;
static const long OFF_RES = (long)NTc * DOUTc;                   // 16777216
static const long OFF_ATT = OFF_RES + (long)NTc * DKc;           // 25165824

#define INV_TEMP 0.04419417382415922f   // 1/sqrt(512)

// ---------------------------------------------------------------------------
// Scratch (static device globals — no allocation at runtime)
// ---------------------------------------------------------------------------
__device__ __align__(16) float g_qp [(size_t)NTc * DKc];   // qp; later t1 (attn@V out)
__device__ __align__(16) float g_kp [(size_t)NTc * DKc];   // kp; later t2 (MLP hidden)
__device__ __align__(16) float g_vp [(size_t)NTc * DVc];
__device__ __align__(16) float g_vpT[(size_t)DVc * NTc];   // vp^T  [512, 16384]
__device__ __align__(16) float g_wqT[(size_t)DKc * DMc];   // Wq^T  [512, 1024]
__device__ __align__(16) float g_wkT[(size_t)DKc * DMc];
__device__ __align__(16) float g_wvT[(size_t)DVc * DMc];
__device__ __align__(16) float g_w1T[(size_t)DVc * DVc];   // W1^T  [512, 512]
__device__ __align__(16) float g_w2T[(size_t)DOUTc * DVc]; // W2^T  [1024, 512]

// ---------------------------------------------------------------------------
// tf32 helpers (arch-portable: cvt sm_80+, mma.sync m16n8k8 sm_80+)
// ---------------------------------------------------------------------------
__device__ __forceinline__ uint32_t f2tf32(float f) {
    uint32_t r;
    asm("cvt.rna.tf32.f32 %0, %1;" : "=r"(r) : "f"(f));
    return r;
}

__device__ __forceinline__ void mma_16x8x8(float* c, const uint32_t* a, const uint32_t* b) {
    asm volatile(
        "mma.sync.aligned.m16n8k8.row.col.f32.tf32.tf32.f32 "
        "{%0,%1,%2,%3}, {%4,%5,%6,%7}, {%8,%9}, {%0,%1,%2,%3};"
        : "+f"(c[0]), "+f"(c[1]), "+f"(c[2]), "+f"(c[3])
        : "r"(a[0]), "r"(a[1]), "r"(a[2]), "r"(a[3]), "r"(b[0]), "r"(b[1]));
}

// ---------------------------------------------------------------------------
// tf32 mma.sync GEMM: C[M,N] = alpha * A[M,K] @ Bt[N,K]^T (+bias) (+relu)
//   A : row-major [M,K], lda = K
//   Bt: row-major [N, ldB] (row n holds the K-vector of column n) = "col" B
//   C : row-major [M,N]
// BM=BN=128, BK=16, 256 threads (8 warps, 4x2), 32x64 per warp.
// Double-buffered smem ([k][m] / [k][n], +8 pad -> conflict-free frag LDS),
// register-staged global prefetch, tf32 cvt at STS, one barrier per K-tile.
// ---------------------------------------------------------------------------
#define BM 128
#define BN 128
#define BK 16
#define LDP 136   // row pad: 128+8 -> tig quad offsets land in disjoint bank octets

template<bool BIAS, bool RELU>
__global__ __launch_bounds__(256, 2)
void mma_gemm(const float* __restrict__ A, const float* __restrict__ Bt,
              const float* __restrict__ bias, float* __restrict__ C,
              int M, int N, int K, int ldB,
              long sA, long sB, long sC, float alpha)
{
    A  += (long)blockIdx.z * sA;
    Bt += (long)blockIdx.z * sB;
    C  += (long)blockIdx.z * sC;

    __shared__ float As[2][BK][LDP];
    __shared__ float Bs[2][BK][LDP];

    const int tid  = threadIdx.x;
    const int wid  = tid >> 5;
    const int lane = tid & 31;
    const int g    = lane >> 2;      // groupID 0..7
    const int tg   = lane & 3;       // thread-in-group 0..3
    const int mw   = (wid & 3) * 32; // warp m-offset in tile
    const int nw   = (wid >> 2) * 64;// warp n-offset in tile
    const int m0   = blockIdx.y * BM;
    const int n0   = blockIdx.x * BN;

    // loader indices: 512 float4 per 128x16 operand tile, 2 per thread
    const int aRow = tid >> 2;           // 0..63 (second chunk +64)
    const int aK4  = (tid & 3) << 2;     // 0,4,8,12

    float acc[2][8][4];
#pragma unroll
    for (int i = 0; i < 2; i++)
#pragma unroll
        for (int j = 0; j < 8; j++)
#pragma unroll
            for (int r = 0; r < 4; r++) acc[i][j][r] = 0.f;

    float4 av0, av1, bv0, bv1;

    // ---- prologue: LDG tile 0
    av0 = *reinterpret_cast<const float4*>(A  + (long)(m0 + aRow)      * K   + aK4);
    av1 = *reinterpret_cast<const float4*>(A  + (long)(m0 + aRow + 64) * K   + aK4);
    bv0 = *reinterpret_cast<const float4*>(Bt + (long)(n0 + aRow)      * ldB + aK4);
    bv1 = *reinterpret_cast<const float4*>(Bt + (long)(n0 + aRow + 64) * ldB + aK4);
    // ---- cvt+STS tile 0 -> buffer 0 (transposed [k][m], [k][n])
    As[0][aK4 + 0][aRow] = __uint_as_float(f2tf32(av0.x));
    As[0][aK4 + 1][aRow] = __uint_as_float(f2tf32(av0.y));
    As[0][aK4 + 2][aRow] = __uint_as_float(f2tf32(av0.z));
    As[0][aK4 + 3][aRow] = __uint_as_float(f2tf32(av0.w));
    As[0][aK4 + 0][aRow + 64] = __uint_as_float(f2tf32(av1.x));
    As[0][aK4 + 1][aRow + 64] = __uint_as_float(f2tf32(av1.y));
    As[0][aK4 + 2][aRow + 64] = __uint_as_float(f2tf32(av1.z));
    As[0][aK4 + 3][aRow + 64] = __uint_as_float(f2tf32(av1.w));
    Bs[0][aK4 + 0][aRow] = __uint_as_float(f2tf32(bv0.x));
    Bs[0][aK4 + 1][aRow] = __uint_as_float(f2tf32(bv0.y));
    Bs[0][aK4 + 2][aRow] = __uint_as_float(f2tf32(bv0.z));
    Bs[0][aK4 + 3][aRow] = __uint_as_float(f2tf32(bv0.w));
    Bs[0][aK4 + 0][aRow + 64] = __uint_as_float(f2tf32(bv1.x));
    Bs[0][aK4 + 1][aRow + 64] = __uint_as_float(f2tf32(bv1.y));
    Bs[0][aK4 + 2][aRow + 64] = __uint_as_float(f2tf32(bv1.z));
    Bs[0][aK4 + 3][aRow + 64] = __uint_as_float(f2tf32(bv1.w));
    __syncthreads();

    const int T = K / BK;
    for (int it = 0; it < T; it++) {
        const int cur = it & 1;

        // ---- prefetch next tile into registers (overlaps compute)
        if (it + 1 < T) {
            const int kc = (it + 1) * BK;
            av0 = *reinterpret_cast<const float4*>(A  + (long)(m0 + aRow)      * K   + kc + aK4);
            av1 = *reinterpret_cast<const float4*>(A  + (long)(m0 + aRow + 64) * K   + kc + aK4);
            bv0 = *reinterpret_cast<const float4*>(Bt + (long)(n0 + aRow)      * ldB + kc + aK4);
            bv1 = *reinterpret_cast<const float4*>(Bt + (long)(n0 + aRow + 64) * ldB + kc + aK4);
        }

        // ---- compute: 2 k-steps of 8, 16 mmas each
#pragma unroll
        for (int kb = 0; kb < BK; kb += 8) {
            uint32_t a[2][4];
#pragma unroll
            for (int mi = 0; mi < 2; mi++) {
                const int mr = mw + mi * 16;
                a[mi][0] = __float_as_uint(As[cur][kb + tg    ][mr + g    ]);
                a[mi][1] = __float_as_uint(As[cur][kb + tg    ][mr + g + 8]);
                a[mi][2] = __float_as_uint(As[cur][kb + tg + 4][mr + g    ]);
                a[mi][3] = __float_as_uint(As[cur][kb + tg + 4][mr + g + 8]);
            }
            uint32_t b[8][2];
#pragma unroll
            for (int ni = 0; ni < 8; ni++) {
                b[ni][0] = __float_as_uint(Bs[cur][kb + tg    ][nw + ni * 8 + g]);
                b[ni][1] = __float_as_uint(Bs[cur][kb + tg + 4][nw + ni * 8 + g]);
            }
#pragma unroll
            for (int mi = 0; mi < 2; mi++)
#pragma unroll
                for (int ni = 0; ni < 8; ni++)
                    mma_16x8x8(acc[mi][ni], a[mi], b[ni]);
        }

        // ---- store prefetched tile into other buffer, single barrier
        if (it + 1 < T) {
            const int nx = cur ^ 1;
            As[nx][aK4 + 0][aRow] = __uint_as_float(f2tf32(av0.x));
            As[nx][aK4 + 1][aRow] = __uint_as_float(f2tf32(av0.y));
            As[nx][aK4 + 2][aRow] = __uint_as_float(f2tf32(av0.z));
            As[nx][aK4 + 3][aRow] = __uint_as_float(f2tf32(av0.w));
            As[nx][aK4 + 0][aRow + 64] = __uint_as_float(f2tf32(av1.x));
            As[nx][aK4 + 1][aRow + 64] = __uint_as_float(f2tf32(av1.y));
            As[nx][aK4 + 2][aRow + 64] = __uint_as_float(f2tf32(av1.z));
            As[nx][aK4 + 3][aRow + 64] = __uint_as_float(f2tf32(av1.w));
            Bs[nx][aK4 + 0][aRow] = __uint_as_float(f2tf32(bv0.x));
            Bs[nx][aK4 + 1][aRow] = __uint_as_float(f2tf32(bv0.y));
            Bs[nx][aK4 + 2][aRow] = __uint_as_float(f2tf32(bv0.z));
            Bs[nx][aK4 + 3][aRow] = __uint_as_float(f2tf32(bv0.w));
            Bs[nx][aK4 + 0][aRow + 64] = __uint_as_float(f2tf32(bv1.x));
            Bs[nx][aK4 + 1][aRow + 64] = __uint_as_float(f2tf32(bv1.y));
            Bs[nx][aK4 + 2][aRow + 64] = __uint_as_float(f2tf32(bv1.z));
            Bs[nx][aK4 + 3][aRow + 64] = __uint_as_float(f2tf32(bv1.w));
            __syncthreads();
        }
    }

    // ---- epilogue: c0/c1 -> row g, cols 2tg/2tg+1; c2/c3 -> row g+8
#pragma unroll
    for (int mi = 0; mi < 2; mi++) {
#pragma unroll
        for (int half = 0; half < 2; half++) {
            const long row = m0 + mw + mi * 16 + g + half * 8;
#pragma unroll
            for (int ni = 0; ni < 8; ni++) {
                const int col = n0 + nw + ni * 8 + 2 * tg;
                float2 r;
                r.x = acc[mi][ni][half * 2 + 0] * alpha;
                r.y = acc[mi][ni][half * 2 + 1] * alpha;
                if (BIAS) {
                    float2 b2v = *reinterpret_cast<const float2*>(bias + col);
                    r.x += b2v.x; r.y += b2v.y;
                }
                if (RELU) { r.x = fmaxf(r.x, 0.f); r.y = fmaxf(r.y, 0.f); }
                *reinterpret_cast<float2*>(C + row * (long)N + col) = r;
            }
        }
    }
}

// ---------------------------------------------------------------------------
// 32x32 tiled transpose: out[C,R] = in[R,C]^T. R,C multiples of 32.
// ---------------------------------------------------------------------------
__global__ __launch_bounds__(256)
void transpose32(const float* __restrict__ in, float* __restrict__ out, int R, int C)
{
    __shared__ float t[32][33];
    int c0 = blockIdx.x * 32, r0 = blockIdx.y * 32;
#pragma unroll
    for (int i = 0; i < 32; i += 8)
        t[threadIdx.y + i][threadIdx.x] = in[(long)(r0 + threadIdx.y + i) * C + c0 + threadIdx.x];
    __syncthreads();
#pragma unroll
    for (int i = 0; i < 32; i += 8)
        out[(long)(c0 + threadIdx.y + i) * R + r0 + threadIdx.x] = t[threadIdx.x][threadIdx.y + i];
}

// ---------------------------------------------------------------------------
// LayerNorm D=512 (unchanged from passing R4 kernel)
// ---------------------------------------------------------------------------
__global__ __launch_bounds__(128)
void ln512_kernel(const float* __restrict__ X,
                  const float* __restrict__ gam, const float* __restrict__ bet,
                  float* __restrict__ Y, float* __restrict__ res)
{
    long row = blockIdx.x;
    const int t = threadIdx.x;
    float4 v = reinterpret_cast<const float4*>(X + row * 512)[t];

    float s  = v.x + v.y + v.z + v.w;
    float sq = v.x * v.x + v.y * v.y + v.z * v.z + v.w * v.w;
#pragma unroll
    for (int o = 16; o > 0; o >>= 1) {
        s  += __shfl_xor_sync(0xffffffffu, s, o);
        sq += __shfl_xor_sync(0xffffffffu, sq, o);
    }
    __shared__ float sh_s[4], sh_q[4];
    int w = t >> 5, l = t & 31;
    if (l == 0) { sh_s[w] = s; sh_q[w] = sq; }
    __syncthreads();
    s  = sh_s[0] + sh_s[1] + sh_s[2] + sh_s[3];
    sq = sh_q[0] + sh_q[1] + sh_q[2] + sh_q[3];

    float mean = s * (1.f / 512.f);
    float var  = sq * (1.f / 512.f) - mean * mean;
    float rs   = rsqrtf(var + 1e-6f);

    if (res) reinterpret_cast<float4*>(res + row * 512)[t] = v;

    float4 g4 = reinterpret_cast<const float4*>(gam)[t];
    float4 b4 = reinterpret_cast<const float4*>(bet)[t];
    float4 o;
    o.x = (v.x - mean) * rs * g4.x + b4.x;
    o.y = (v.y - mean) * rs * g4.y + b4.y;
    o.z = (v.z - mean) * rs * g4.z + b4.z;
    o.w = (v.w - mean) * rs * g4.w + b4.w;
    reinterpret_cast<float4*>(Y + row * 512)[t] = o;
}

// ---------------------------------------------------------------------------
// Mask + softmax rows of 2048, in place (unchanged from passing R4 kernel)
// ---------------------------------------------------------------------------
__global__ __launch_bounds__(256)
void softmax2048_kernel(float* __restrict__ Scores, const int* __restrict__ mask)
{
    long row = blockIdx.x;
    float* s      = Scores + row * 2048;
    const int* m  = mask   + row * 2048;
    const int t = threadIdx.x;

    float vals[8];
    float mx = -1e30f;
#pragma unroll
    for (int i = 0; i < 8; i++) {
        int c = t + i * 256;
        float x = s[c];
        if (m[c] == 0) x = -1e9f;
        vals[i] = x;
        mx = fmaxf(mx, x);
    }
    __shared__ float sh[8];
#pragma unroll
    for (int o = 16; o > 0; o >>= 1) mx = fmaxf(mx, __shfl_xor_sync(0xffffffffu, mx, o));
    int w = t >> 5, l = t & 31;
    if (l == 0) sh[w] = mx;
    __syncthreads();
    mx = sh[0];
#pragma unroll
    for (int i = 1; i < 8; i++) mx = fmaxf(mx, sh[i]);
    __syncthreads();

    float sum = 0.f;
#pragma unroll
    for (int i = 0; i < 8; i++) {
        vals[i] = __expf(vals[i] - mx);
        sum += vals[i];
    }
#pragma unroll
    for (int o = 16; o > 0; o >>= 1) sum += __shfl_xor_sync(0xffffffffu, sum, o);
    if (l == 0) sh[w] = sum;
    __syncthreads();
    sum = sh[0] + sh[1] + sh[2] + sh[3] + sh[4] + sh[5] + sh[6] + sh[7];

    float inv = 1.f / sum;
#pragma unroll
    for (int i = 0; i < 8; i++) s[t + i * 256] = vals[i] * inv;
}

// ---------------------------------------------------------------------------
// Launch
// ---------------------------------------------------------------------------
extern "C" void kernel_launch(void* const* d_in, const int* in_sizes, int n_in,
                              void* d_out_, int out_size)
{
    const float* q    = (const float*)d_in[0];
    const float* k    = (const float*)d_in[1];
    const float* v    = (const float*)d_in[2];
    const int*   mask = (const int*)  d_in[3];
    const float* Wq   = (const float*)d_in[4];
    const float* bq   = (const float*)d_in[5];
    const float* Wk   = (const float*)d_in[6];
    const float* bk   = (const float*)d_in[7];
    const float* Wv   = (const float*)d_in[8];
    const float* bv   = (const float*)d_in[9];
    const float* gq   = (const float*)d_in[10];
    const float* beq  = (const float*)d_in[11];
    const float* gk   = (const float*)d_in[12];
    const float* bek  = (const float*)d_in[13];
    const float* gv   = (const float*)d_in[14];
    const float* bev  = (const float*)d_in[15];
    const float* W1   = (const float*)d_in[16];
    const float* b1   = (const float*)d_in[17];
    const float* W2   = (const float*)d_in[18];
    const float* b2   = (const float*)d_in[19];
    float* out = (float*)d_out_;

    float *qp, *kp, *vp, *vpT, *wqT, *wkT, *wvT, *w1T, *w2T;
    cudaGetSymbolAddress((void**)&qp,  g_qp);
    cudaGetSymbolAddress((void**)&kp,  g_kp);
    cudaGetSymbolAddress((void**)&vp,  g_vp);
    cudaGetSymbolAddress((void**)&vpT, g_vpT);
    cudaGetSymbolAddress((void**)&wqT, g_wqT);
    cudaGetSymbolAddress((void**)&wkT, g_wkT);
    cudaGetSymbolAddress((void**)&wvT, g_wvT);
    cudaGetSymbolAddress((void**)&w1T, g_w1T);
    cudaGetSymbolAddress((void**)&w2T, g_w2T);
    float* t1 = qp;   // qp dead after scores GEMM
    float* t2 = kp;   // kp dead after scores GEMM

    dim3 tb(32, 8);
    dim3 blk(256);

    // 0) weight transposes -> [N,K] K-major operands
    transpose32<<<dim3(DKc/32,  DMc/32), tb>>>(Wq, wqT, DMc, DKc);
    transpose32<<<dim3(DKc/32,  DMc/32), tb>>>(Wk, wkT, DMc, DKc);
    transpose32<<<dim3(DVc/32,  DMc/32), tb>>>(Wv, wvT, DMc, DVc);
    transpose32<<<dim3(DVc/32,  DVc/32), tb>>>(W1, w1T, DVc, DVc);
    transpose32<<<dim3(DOUTc/32, DVc/32), tb>>>(W2, w2T, DVc, DOUTc);

    // 1-3) QKV projections (+bias): [16384,1024] @ [1024,512]
    mma_gemm<true, false><<<dim3(DKc/BN, NTc/BM, 1), blk>>>(
        q, wqT, bq, qp, NTc, DKc, DMc, DMc, 0, 0, 0, 1.f);
    mma_gemm<true, false><<<dim3(DKc/BN, NTc/BM, 1), blk>>>(
        k, wkT, bk, kp, NTc, DKc, DMc, DMc, 0, 0, 0, 1.f);
    mma_gemm<true, false><<<dim3(DVc/BN, NTc/BM, 1), blk>>>(
        v, wvT, bv, vp, NTc, DVc, DMc, DMc, 0, 0, 0, 1.f);

    // 4-6) LayerNorm (in place). q-LN also emits residual.
    ln512_kernel<<<NTc, 128>>>(qp, gq, beq, qp, out + OFF_RES);
    ln512_kernel<<<NTc, 128>>>(kp, gk, bek, kp, nullptr);
    ln512_kernel<<<NTc, 128>>>(vp, gv, bev, vp, nullptr);

    // 6b) vp^T for the attn@V B-operand
    transpose32<<<dim3(DVc/32, NTc/32), tb>>>(vp, vpT, NTc, DVc);

    // 7) scores = (qn @ kn^T) / sqrt(dk), batched -> attn region
    mma_gemm<false, false><<<dim3(Sc/BN, Sc/BM, Bc), blk>>>(
        qp, kp, nullptr, out + OFF_ATT, Sc, Sc, DKc, DKc,
        (long)Sc * DKc, (long)Sc * DKc, (long)Sc * Sc, INV_TEMP);

    // 8) mask + softmax in place
    softmax2048_kernel<<<NTc, 256>>>(out + OFF_ATT, mask);

    // 9) out1 = attn @ vn  (Bt = vpT, rows length NTc; batch offset Sc cols)
    mma_gemm<false, false><<<dim3(DVc/BN, Sc/BM, Bc), blk>>>(
        out + OFF_ATT, vpT, nullptr, t1, Sc, DVc, Sc, NTc,
        (long)Sc * Sc, (long)Sc, (long)Sc * DVc, 1.f);

    // 10) h = relu(out1 @ W1 + b1)
    mma_gemm<true, true><<<dim3(DVc/BN, NTc/BM, 1), blk>>>(
        t1, w1T, b1, t2, NTc, DVc, DVc, DVc, 0, 0, 0, 1.f);

    // 11) out = h @ W2 + b2
    mma_gemm<true, false><<<dim3(DOUTc/BN, NTc/BM, 1), blk>>>(
        t2, w2T, b2, out + OFF_OUT, NTc, DOUTc, DVc, DVc, 0, 0, 0, 1.f);
}

// round 9
// speedup vs baseline: 2.7272x; 1.0569x over previous
#include <cuda_runtime.h>
#include <math.h>
#include <stdint.h>

// ---------------------------------------------------------------------------
// Problem constants
// ---------------------------------------------------------------------------
#define Bc    8
#define Sc    2048
#define DMc   1024
#define DKc   512
#define DVc   512
#define DOUTc 1024
#define NTc   (Bc * Sc)              // 16384 tokens

static const long OFF_OUT = 0L;
static const long OFF_RES = (long)NTc * DOUTc;                   // 16777216
static const long OFF_ATT = OFF_RES + (long)NTc * DKc;           // 25165824

#define INV_TEMP 0.04419417382415922f   // 1/sqrt(512)

// ---------------------------------------------------------------------------
// Scratch (static device globals — no allocation at runtime)
// ---------------------------------------------------------------------------
__device__ __align__(16) float g_qp [(size_t)NTc * DKc];   // qp; later t1 (attn@V out)
__device__ __align__(16) float g_kp [(size_t)NTc * DKc];   // kp; later t2 (MLP hidden)
__device__ __align__(16) float g_vp [(size_t)NTc * DVc];
__device__ __align__(16) float g_vpT[(size_t)DVc * NTc];   // vp^T  [512, 16384]
__device__ __align__(16) float g_wqT[(size_t)DKc * DMc];   // Wq^T  [512, 1024]
__device__ __align__(16) float g_wkT[(size_t)DKc * DMc];
__device__ __align__(16) float g_wvT[(size_t)DVc * DMc];
__device__ __align__(16) float g_w1T[(size_t)DVc * DVc];   // W1^T  [512, 512]
__device__ __align__(16) float g_w2T[(size_t)DOUTc * DVc]; // W2^T  [1024, 512]

// ---------------------------------------------------------------------------
// tf32 helpers (arch-portable: cvt sm_80+, mma.sync m16n8k8 sm_80+)
// ---------------------------------------------------------------------------
__device__ __forceinline__ uint32_t f2tf32(float f) {
    uint32_t r;
    asm("cvt.rna.tf32.f32 %0, %1;" : "=r"(r) : "f"(f));
    return r;
}

__device__ __forceinline__ void mma_16x8x8(float* c, const uint32_t* a, const uint32_t* b) {
    asm volatile(
        "mma.sync.aligned.m16n8k8.row.col.f32.tf32.tf32.f32 "
        "{%0,%1,%2,%3}, {%4,%5,%6,%7}, {%8,%9}, {%0,%1,%2,%3};"
        : "+f"(c[0]), "+f"(c[1]), "+f"(c[2]), "+f"(c[3])
        : "r"(a[0]), "r"(a[1]), "r"(a[2]), "r"(a[3]), "r"(b[0]), "r"(b[1]));
}

// ---------------------------------------------------------------------------
// Fragment-major permuted smem layout.
// A value (m,k) [m<128, k<16] -> word index:
//   kt=k>>3 block (stride 1032 = 8 atoms*128 + 8 pad -> de-conflicts STS banks)
//   atom (mt=m>>4) stride 128; lane = (m&7)*4 + (k&3); reg = ((k>>2)&1)*2 + ((m>>3)&1)
// B value (n,k) -> kt stride 1032; atom (nt=n>>3) stride 64;
//   lane = (n&7)*4 + (k&3); reg = (k>>2)&1
// Compute side: A frag = one LDS.128 (lane*4), B frag = one LDS.64 (lane*2),
// registers land directly in mma.sync m16n8k8 order (verified vs R6 mapping).
// ---------------------------------------------------------------------------
#define KT_STRIDE 1032
#define OP_WORDS  (2 * KT_STRIDE)   // 2064 words per operand tile

__device__ __forceinline__ int a_word(int m, int k) {
    return (k >> 3) * KT_STRIDE + (m >> 4) * 128
         + ((m & 7) * 4 + (k & 3)) * 4 + ((k >> 2) & 1) * 2 + ((m >> 3) & 1);
}
__device__ __forceinline__ int b_word(int n, int k) {
    return (k >> 3) * KT_STRIDE + (n >> 3) * 64
         + ((n & 7) * 4 + (k & 3)) * 2 + ((k >> 2) & 1);
}

// ---------------------------------------------------------------------------
// tf32 mma.sync GEMM: C[M,N] = alpha * A[M,K] @ Bt[N,K]^T (+bias) (+relu)
// BM=BN=128, BK=16, 256 threads (8 warps, 4x2), 32x64 per warp.
// Double-buffered permuted smem, register-staged global prefetch,
// tf32 cvt at STS, one barrier per K-tile.
// ---------------------------------------------------------------------------
#define BM 128
#define BN 128
#define BK 16

template<bool BIAS, bool RELU>
__global__ __launch_bounds__(256, 2)
void mma_gemm(const float* __restrict__ A, const float* __restrict__ Bt,
              const float* __restrict__ bias, float* __restrict__ C,
              int M, int N, int K, int ldB,
              long sA, long sB, long sC, float alpha)
{
    A  += (long)blockIdx.z * sA;
    Bt += (long)blockIdx.z * sB;
    C  += (long)blockIdx.z * sC;

    __shared__ __align__(16) float As[2][OP_WORDS];
    __shared__ __align__(16) float Bs[2][OP_WORDS];

    const int tid  = threadIdx.x;
    const int wid  = tid >> 5;
    const int lane = tid & 31;
    const int g    = lane >> 2;      // groupID 0..7
    const int tg   = lane & 3;       // thread-in-group 0..3
    const int mw   = (wid & 3) * 32; // warp m-offset in tile
    const int nw   = (wid >> 2) * 64;// warp n-offset in tile
    const int m0   = blockIdx.y * BM;
    const int n0   = blockIdx.x * BN;

    // loader indices: 512 float4 per 128x16 operand tile, 2 per thread
    const int aRow = tid >> 2;           // 0..63 (second chunk +64)
    const int aK4  = (tid & 3) << 2;     // 0,4,8,12

    // precomputed store word-indices (k varies by +1 within the float4)
    int awl[4], awh[4], bwl[4], bwh[4];
#pragma unroll
    for (int j = 0; j < 4; j++) {
        awl[j] = a_word(aRow,      aK4 + j);
        awh[j] = a_word(aRow + 64, aK4 + j);
        bwl[j] = b_word(aRow,      aK4 + j);
        bwh[j] = b_word(aRow + 64, aK4 + j);
    }

    float acc[2][8][4];
#pragma unroll
    for (int i = 0; i < 2; i++)
#pragma unroll
        for (int j = 0; j < 8; j++)
#pragma unroll
            for (int r = 0; r < 4; r++) acc[i][j][r] = 0.f;

    float4 av0, av1, bv0, bv1;

    // ---- prologue: LDG tile 0
    av0 = *reinterpret_cast<const float4*>(A  + (long)(m0 + aRow)      * K   + aK4);
    av1 = *reinterpret_cast<const float4*>(A  + (long)(m0 + aRow + 64) * K   + aK4);
    bv0 = *reinterpret_cast<const float4*>(Bt + (long)(n0 + aRow)      * ldB + aK4);
    bv1 = *reinterpret_cast<const float4*>(Bt + (long)(n0 + aRow + 64) * ldB + aK4);
    {
        const float* af0 = &av0.x; const float* af1 = &av1.x;
        const float* bf0 = &bv0.x; const float* bf1 = &bv1.x;
#pragma unroll
        for (int j = 0; j < 4; j++) {
            As[0][awl[j]] = __uint_as_float(f2tf32(af0[j]));
            As[0][awh[j]] = __uint_as_float(f2tf32(af1[j]));
            Bs[0][bwl[j]] = __uint_as_float(f2tf32(bf0[j]));
            Bs[0][bwh[j]] = __uint_as_float(f2tf32(bf1[j]));
        }
    }
    __syncthreads();

    const int T = K / BK;
    for (int it = 0; it < T; it++) {
        const int cur = it & 1;

        // ---- prefetch next tile into registers (overlaps compute)
        if (it + 1 < T) {
            const int kc = (it + 1) * BK;
            av0 = *reinterpret_cast<const float4*>(A  + (long)(m0 + aRow)      * K   + kc + aK4);
            av1 = *reinterpret_cast<const float4*>(A  + (long)(m0 + aRow + 64) * K   + kc + aK4);
            bv0 = *reinterpret_cast<const float4*>(Bt + (long)(n0 + aRow)      * ldB + kc + aK4);
            bv1 = *reinterpret_cast<const float4*>(Bt + (long)(n0 + aRow + 64) * ldB + kc + aK4);
        }

        // ---- compute: 2 kt-steps (k8 each); vector frag loads
#pragma unroll
        for (int kt = 0; kt < 2; kt++) {
            const float* Ab = &As[cur][kt * KT_STRIDE];
            const float* Bb = &Bs[cur][kt * KT_STRIDE];
            uint32_t a[2][4];
#pragma unroll
            for (int mi = 0; mi < 2; mi++) {
                const int mt = (wid & 3) * 2 + mi;
                float4 f = *reinterpret_cast<const float4*>(Ab + mt * 128 + lane * 4);
                a[mi][0] = __float_as_uint(f.x);
                a[mi][1] = __float_as_uint(f.y);
                a[mi][2] = __float_as_uint(f.z);
                a[mi][3] = __float_as_uint(f.w);
            }
            uint32_t b[8][2];
#pragma unroll
            for (int ni = 0; ni < 8; ni++) {
                const int nt = (wid >> 2) * 8 + ni;
                float2 f = *reinterpret_cast<const float2*>(Bb + nt * 64 + lane * 2);
                b[ni][0] = __float_as_uint(f.x);
                b[ni][1] = __float_as_uint(f.y);
            }
#pragma unroll
            for (int mi = 0; mi < 2; mi++)
#pragma unroll
                for (int ni = 0; ni < 8; ni++)
                    mma_16x8x8(acc[mi][ni], a[mi], b[ni]);
        }

        // ---- store prefetched tile into other buffer, single barrier
        if (it + 1 < T) {
            const int nx = cur ^ 1;
            const float* af0 = &av0.x; const float* af1 = &av1.x;
            const float* bf0 = &bv0.x; const float* bf1 = &bv1.x;
#pragma unroll
            for (int j = 0; j < 4; j++) {
                As[nx][awl[j]] = __uint_as_float(f2tf32(af0[j]));
                As[nx][awh[j]] = __uint_as_float(f2tf32(af1[j]));
                Bs[nx][bwl[j]] = __uint_as_float(f2tf32(bf0[j]));
                Bs[nx][bwh[j]] = __uint_as_float(f2tf32(bf1[j]));
            }
            __syncthreads();
        }
    }

    // ---- epilogue: c0/c1 -> row g, cols 2tg/2tg+1; c2/c3 -> row g+8
#pragma unroll
    for (int mi = 0; mi < 2; mi++) {
#pragma unroll
        for (int half = 0; half < 2; half++) {
            const long row = m0 + mw + mi * 16 + g + half * 8;
#pragma unroll
            for (int ni = 0; ni < 8; ni++) {
                const int col = n0 + nw + ni * 8 + 2 * tg;
                float2 r;
                r.x = acc[mi][ni][half * 2 + 0] * alpha;
                r.y = acc[mi][ni][half * 2 + 1] * alpha;
                if (BIAS) {
                    float2 b2v = *reinterpret_cast<const float2*>(bias + col);
                    r.x += b2v.x; r.y += b2v.y;
                }
                if (RELU) { r.x = fmaxf(r.x, 0.f); r.y = fmaxf(r.y, 0.f); }
                *reinterpret_cast<float2*>(C + row * (long)N + col) = r;
            }
        }
    }
}

// ---------------------------------------------------------------------------
// 32x32 tiled transpose: out[C,R] = in[R,C]^T. R,C multiples of 32.
// ---------------------------------------------------------------------------
__global__ __launch_bounds__(256)
void transpose32(const float* __restrict__ in, float* __restrict__ out, int R, int C)
{
    __shared__ float t[32][33];
    int c0 = blockIdx.x * 32, r0 = blockIdx.y * 32;
#pragma unroll
    for (int i = 0; i < 32; i += 8)
        t[threadIdx.y + i][threadIdx.x] = in[(long)(r0 + threadIdx.y + i) * C + c0 + threadIdx.x];
    __syncthreads();
#pragma unroll
    for (int i = 0; i < 32; i += 8)
        out[(long)(c0 + threadIdx.y + i) * R + r0 + threadIdx.x] = t[threadIdx.x][threadIdx.y + i];
}

// ---------------------------------------------------------------------------
// LayerNorm D=512
// ---------------------------------------------------------------------------
__global__ __launch_bounds__(128)
void ln512_kernel(const float* __restrict__ X,
                  const float* __restrict__ gam, const float* __restrict__ bet,
                  float* __restrict__ Y, float* __restrict__ res)
{
    long row = blockIdx.x;
    const int t = threadIdx.x;
    float4 v = reinterpret_cast<const float4*>(X + row * 512)[t];

    float s  = v.x + v.y + v.z + v.w;
    float sq = v.x * v.x + v.y * v.y + v.z * v.z + v.w * v.w;
#pragma unroll
    for (int o = 16; o > 0; o >>= 1) {
        s  += __shfl_xor_sync(0xffffffffu, s, o);
        sq += __shfl_xor_sync(0xffffffffu, sq, o);
    }
    __shared__ float sh_s[4], sh_q[4];
    int w = t >> 5, l = t & 31;
    if (l == 0) { sh_s[w] = s; sh_q[w] = sq; }
    __syncthreads();
    s  = sh_s[0] + sh_s[1] + sh_s[2] + sh_s[3];
    sq = sh_q[0] + sh_q[1] + sh_q[2] + sh_q[3];

    float mean = s * (1.f / 512.f);
    float var  = sq * (1.f / 512.f) - mean * mean;
    float rs   = rsqrtf(var + 1e-6f);

    if (res) reinterpret_cast<float4*>(res + row * 512)[t] = v;

    float4 g4 = reinterpret_cast<const float4*>(gam)[t];
    float4 b4 = reinterpret_cast<const float4*>(bet)[t];
    float4 o;
    o.x = (v.x - mean) * rs * g4.x + b4.x;
    o.y = (v.y - mean) * rs * g4.y + b4.y;
    o.z = (v.z - mean) * rs * g4.z + b4.z;
    o.w = (v.w - mean) * rs * g4.w + b4.w;
    reinterpret_cast<float4*>(Y + row * 512)[t] = o;
}

// ---------------------------------------------------------------------------
// Mask + softmax rows of 2048, in place
// ---------------------------------------------------------------------------
__global__ __launch_bounds__(256)
void softmax2048_kernel(float* __restrict__ Scores, const int* __restrict__ mask)
{
    long row = blockIdx.x;
    float* s      = Scores + row * 2048;
    const int* m  = mask   + row * 2048;
    const int t = threadIdx.x;

    float vals[8];
    float mx = -1e30f;
#pragma unroll
    for (int i = 0; i < 8; i++) {
        int c = t + i * 256;
        float x = s[c];
        if (m[c] == 0) x = -1e9f;
        vals[i] = x;
        mx = fmaxf(mx, x);
    }
    __shared__ float sh[8];
#pragma unroll
    for (int o = 16; o > 0; o >>= 1) mx = fmaxf(mx, __shfl_xor_sync(0xffffffffu, mx, o));
    int w = t >> 5, l = t & 31;
    if (l == 0) sh[w] = mx;
    __syncthreads();
    mx = sh[0];
#pragma unroll
    for (int i = 1; i < 8; i++) mx = fmaxf(mx, sh[i]);
    __syncthreads();

    float sum = 0.f;
#pragma unroll
    for (int i = 0; i < 8; i++) {
        vals[i] = __expf(vals[i] - mx);
        sum += vals[i];
    }
#pragma unroll
    for (int o = 16; o > 0; o >>= 1) sum += __shfl_xor_sync(0xffffffffu, sum, o);
    if (l == 0) sh[w] = sum;
    __syncthreads();
    sum = sh[0] + sh[1] + sh[2] + sh[3] + sh[4] + sh[5] + sh[6] + sh[7];

    float inv = 1.f / sum;
#pragma unroll
    for (int i = 0; i < 8; i++) s[t + i * 256] = vals[i] * inv;
}

// ---------------------------------------------------------------------------
// Launch.  Order chosen so ncu (-s 5 -c 1) captures launch #5 = V-proj GEMM.
// ---------------------------------------------------------------------------
extern "C" void kernel_launch(void* const* d_in, const int* in_sizes, int n_in,
                              void* d_out_, int out_size)
{
    const float* q    = (const float*)d_in[0];
    const float* k    = (const float*)d_in[1];
    const float* v    = (const float*)d_in[2];
    const int*   mask = (const int*)  d_in[3];
    const float* Wq   = (const float*)d_in[4];
    const float* bq   = (const float*)d_in[5];
    const float* Wk   = (const float*)d_in[6];
    const float* bk   = (const float*)d_in[7];
    const float* Wv   = (const float*)d_in[8];
    const float* bv   = (const float*)d_in[9];
    const float* gq   = (const float*)d_in[10];
    const float* beq  = (const float*)d_in[11];
    const float* gk   = (const float*)d_in[12];
    const float* bek  = (const float*)d_in[13];
    const float* gv   = (const float*)d_in[14];
    const float* bev  = (const float*)d_in[15];
    const float* W1   = (const float*)d_in[16];
    const float* b1   = (const float*)d_in[17];
    const float* W2   = (const float*)d_in[18];
    const float* b2   = (const float*)d_in[19];
    float* out = (float*)d_out_;

    float *qp, *kp, *vp, *vpT, *wqT, *wkT, *wvT, *w1T, *w2T;
    cudaGetSymbolAddress((void**)&qp,  g_qp);
    cudaGetSymbolAddress((void**)&kp,  g_kp);
    cudaGetSymbolAddress((void**)&vp,  g_vp);
    cudaGetSymbolAddress((void**)&vpT, g_vpT);
    cudaGetSymbolAddress((void**)&wqT, g_wqT);
    cudaGetSymbolAddress((void**)&wkT, g_wkT);
    cudaGetSymbolAddress((void**)&wvT, g_wvT);
    cudaGetSymbolAddress((void**)&w1T, g_w1T);
    cudaGetSymbolAddress((void**)&w2T, g_w2T);
    float* t1 = qp;   // qp dead after scores GEMM
    float* t2 = kp;   // kp dead after scores GEMM

    dim3 tb(32, 8);
    dim3 blk(256);

    // 0-2) QKV weight transposes
    transpose32<<<dim3(DKc/32,  DMc/32), tb>>>(Wq, wqT, DMc, DKc);   // #0
    transpose32<<<dim3(DKc/32,  DMc/32), tb>>>(Wk, wkT, DMc, DKc);   // #1
    transpose32<<<dim3(DVc/32,  DMc/32), tb>>>(Wv, wvT, DMc, DVc);   // #2

    // 3-5) QKV projections (+bias): [16384,1024] @ [1024,512]
    mma_gemm<true, false><<<dim3(DKc/BN, NTc/BM, 1), blk>>>(
        q, wqT, bq, qp, NTc, DKc, DMc, DMc, 0, 0, 0, 1.f);           // #3
    mma_gemm<true, false><<<dim3(DKc/BN, NTc/BM, 1), blk>>>(
        k, wkT, bk, kp, NTc, DKc, DMc, DMc, 0, 0, 0, 1.f);           // #4
    mma_gemm<true, false><<<dim3(DVc/BN, NTc/BM, 1), blk>>>(
        v, wvT, bv, vp, NTc, DVc, DMc, DMc, 0, 0, 0, 1.f);           // #5 <- ncu

    // LayerNorm (in place). q-LN also emits residual.
    ln512_kernel<<<NTc, 128>>>(qp, gq, beq, qp, out + OFF_RES);
    ln512_kernel<<<NTc, 128>>>(kp, gk, bek, kp, nullptr);
    ln512_kernel<<<NTc, 128>>>(vp, gv, bev, vp, nullptr);

    // vp^T for the attn@V B-operand
    transpose32<<<dim3(DVc/32, NTc/32), tb>>>(vp, vpT, NTc, DVc);

    // scores = (qn @ kn^T) / sqrt(dk), batched -> attn region
    mma_gemm<false, false><<<dim3(Sc/BN, Sc/BM, Bc), blk>>>(
        qp, kp, nullptr, out + OFF_ATT, Sc, Sc, DKc, DKc,
        (long)Sc * DKc, (long)Sc * DKc, (long)Sc * Sc, INV_TEMP);

    // mask + softmax in place
    softmax2048_kernel<<<NTc, 256>>>(out + OFF_ATT, mask);

    // MLP weight transposes (first needed below)
    transpose32<<<dim3(DVc/32,  DVc/32), tb>>>(W1, w1T, DVc, DVc);
    transpose32<<<dim3(DOUTc/32, DVc/32), tb>>>(W2, w2T, DVc, DOUTc);

    // out1 = attn @ vn  (Bt = vpT, rows length NTc; batch offset Sc cols)
    mma_gemm<false, false><<<dim3(DVc/BN, Sc/BM, Bc), blk>>>(
        out + OFF_ATT, vpT, nullptr, t1, Sc, DVc, Sc, NTc,
        (long)Sc * Sc, (long)Sc, (long)Sc * DVc, 1.f);

    // h = relu(out1 @ W1 + b1)
    mma_gemm<true, true><<<dim3(DVc/BN, NTc/BM, 1), blk>>>(
        t1, w1T, b1, t2, NTc, DVc, DVc, DVc, 0, 0, 0, 1.f);

    // out = h @ W2 + b2
    mma_gemm<true, false><<<dim3(DOUTc/BN, NTc/BM, 1), blk>>>(
        t2, w2T, b2, out + OFF_OUT, NTc, DOUTc, DVc, DVc, 0, 0, 0, 1.f);
}

// round 11
// speedup vs baseline: 2.9057x; 1.0655x over previous
#include <cuda_runtime.h>
#include <math.h>
#include <stdint.h>

// ---------------------------------------------------------------------------
// Problem constants
// ---------------------------------------------------------------------------
#define Bc    8
#define Sc    2048
#define DMc   1024
#define DKc   512
#define DVc   512
#define DOUTc 1024
#define NTc   (Bc * Sc)              // 16384 tokens

static const long OFF_OUT = 0L;
static const long OFF_RES = (long)NTc * DOUTc;                   // 16777216
static const long OFF_ATT = OFF_RES + (long)NTc * DKc;           // 25165824

#define INV_TEMP 0.04419417382415922f   // 1/sqrt(512)

// ---------------------------------------------------------------------------
// Scratch (static device globals — no allocation at runtime)
// ---------------------------------------------------------------------------
__device__ __align__(16) float g_qp [(size_t)NTc * DKc];   // qp; later t1 (attn@V out)
__device__ __align__(16) float g_kp [(size_t)NTc * DKc];   // kp; later t2 (MLP hidden)
__device__ __align__(16) float g_vp [(size_t)NTc * DVc];
__device__ __align__(16) float g_vpT[(size_t)DVc * NTc];   // vp^T  [512, 16384]
__device__ __align__(16) float g_wqT[(size_t)DKc * DMc];   // Wq^T  [512, 1024]
__device__ __align__(16) float g_wkT[(size_t)DKc * DMc];
__device__ __align__(16) float g_wvT[(size_t)DVc * DMc];
__device__ __align__(16) float g_w1T[(size_t)DVc * DVc];   // W1^T  [512, 512]
__device__ __align__(16) float g_w2T[(size_t)DOUTc * DVc]; // W2^T  [1024, 512]

// ---------------------------------------------------------------------------
// tf32 helpers (arch-portable: cvt sm_80+, mma.sync m16n8k8 sm_80+)
// ---------------------------------------------------------------------------
__device__ __forceinline__ uint32_t f2tf32(float f) {
    uint32_t r;
    asm("cvt.rna.tf32.f32 %0, %1;" : "=r"(r) : "f"(f));
    return r;
}

__device__ __forceinline__ void mma_16x8x8(float* c, const uint32_t* a, const uint32_t* b) {
    asm volatile(
        "mma.sync.aligned.m16n8k8.row.col.f32.tf32.tf32.f32 "
        "{%0,%1,%2,%3}, {%4,%5,%6,%7}, {%8,%9}, {%0,%1,%2,%3};"
        : "+f"(c[0]), "+f"(c[1]), "+f"(c[2]), "+f"(c[3])
        : "r"(a[0]), "r"(a[1]), "r"(a[2]), "r"(a[3]), "r"(b[0]), "r"(b[1]));
}

// ---------------------------------------------------------------------------
// Fragment-major permuted smem layout (verified in R9 run — unchanged).
// A value (m,k) [m<128, k<16] -> word index:
//   kt=k>>3 block (stride 1032); atom (mt=m>>4) stride 128;
//   lane = (m&7)*4 + (k&3); reg = ((k>>2)&1)*2 + ((m>>3)&1)
// B value (n,k) -> kt stride 1032; atom (nt=n>>3) stride 64;
//   lane = (n&7)*4 + (k&3); reg = (k>>2)&1
// Compute side: A frag = one LDS.128 (lane*4), B frag = one LDS.64 (lane*2).
// Note: a_word(m, kq+j) = a_word(m, kq) + 4*j ; b_word(n, kq+j) = b_word(n, kq) + 2*j
// ---------------------------------------------------------------------------
#define KT_STRIDE 1032
#define OP_WORDS  (2 * KT_STRIDE)   // 2064 words per operand tile

__device__ __forceinline__ int a_word(int m, int k) {
    return (k >> 3) * KT_STRIDE + (m >> 4) * 128
         + ((m & 7) * 4 + (k & 3)) * 4 + ((k >> 2) & 1) * 2 + ((m >> 3) & 1);
}
__device__ __forceinline__ int b_word(int n, int k) {
    return (k >> 3) * KT_STRIDE + (n >> 3) * 64
         + ((n & 7) * 4 + (k & 3)) * 2 + ((k >> 2) & 1);
}

// ---------------------------------------------------------------------------
// tf32 mma.sync GEMM: C[M,N] = alpha * A[M,K] @ Bt[N,K]^T (+bias) (+relu)
// BM=BN=128, BK=16, 128 threads (4 warps, 2x2 grid), 64x64 per warp.
// Doubles FLOP per smem byte vs the 8-warp/32x64 config (L1-throughput wall
// measured at 77.7% in R9). Same layout, same K-summation order -> bit-identical.
// ---------------------------------------------------------------------------
#define BM 128
#define BN 128
#define BK 16

template<bool BIAS, bool RELU>
__global__ __launch_bounds__(128, 2)
void mma_gemm(const float* __restrict__ A, const float* __restrict__ Bt,
              const float* __restrict__ bias, float* __restrict__ C,
              int M, int N, int K, int ldB,
              long sA, long sB, long sC, float alpha)
{
    A  += (long)blockIdx.z * sA;
    Bt += (long)blockIdx.z * sB;
    C  += (long)blockIdx.z * sC;

    __shared__ __align__(16) float As[2][OP_WORDS];
    __shared__ __align__(16) float Bs[2][OP_WORDS];

    const int tid  = threadIdx.x;
    const int wid  = tid >> 5;       // 0..3
    const int lane = tid & 31;
    const int g    = lane >> 2;      // groupID 0..7
    const int tg   = lane & 3;       // thread-in-group 0..3
    const int wm   = (wid & 1);      // warp m index (0..1), 64 rows each
    const int wn   = (wid >> 1);     // warp n index (0..1), 64 cols each
    const int m0   = blockIdx.y * BM;
    const int n0   = blockIdx.x * BN;

    // loader: 512 float4 per 128x16 operand tile, 4 per thread (i = 0..3)
    int rowi[4], aw[4], bw[4];
#pragma unroll
    for (int i = 0; i < 4; i++) {
        int idx = i * 128 + tid;
        rowi[i] = idx >> 2;                 // 0..127
        int kq  = (idx & 3) << 2;           // 0,4,8,12
        aw[i] = a_word(rowi[i], kq);
        bw[i] = b_word(rowi[i], kq);
    }
    const int kq0 = (tid & 3) << 2;         // k-quad offset for LDG (same all i)

    float acc[4][8][4];
#pragma unroll
    for (int i = 0; i < 4; i++)
#pragma unroll
        for (int j = 0; j < 8; j++)
#pragma unroll
            for (int r = 0; r < 4; r++) acc[i][j][r] = 0.f;

    float4 av[4], bv[4];

    // ---- prologue: LDG tile 0
#pragma unroll
    for (int i = 0; i < 4; i++) {
        av[i] = *reinterpret_cast<const float4*>(A  + (long)(m0 + rowi[i]) * K   + kq0);
        bv[i] = *reinterpret_cast<const float4*>(Bt + (long)(n0 + rowi[i]) * ldB + kq0);
    }
    // ---- cvt+STS tile 0 -> buffer 0
#pragma unroll
    for (int i = 0; i < 4; i++) {
        const float* af = &av[i].x;
        const float* bf = &bv[i].x;
#pragma unroll
        for (int j = 0; j < 4; j++) {
            As[0][aw[i] + 4 * j] = __uint_as_float(f2tf32(af[j]));
            Bs[0][bw[i] + 2 * j] = __uint_as_float(f2tf32(bf[j]));
        }
    }
    __syncthreads();

    const int T = K / BK;
    for (int it = 0; it < T; it++) {
        const int cur = it & 1;

        // ---- prefetch next tile into registers (overlaps compute)
        if (it + 1 < T) {
            const int kc = (it + 1) * BK;
#pragma unroll
            for (int i = 0; i < 4; i++) {
                av[i] = *reinterpret_cast<const float4*>(A  + (long)(m0 + rowi[i]) * K   + kc + kq0);
                bv[i] = *reinterpret_cast<const float4*>(Bt + (long)(n0 + rowi[i]) * ldB + kc + kq0);
            }
        }

        // ---- compute: 2 kt-steps (k8 each); vector frag loads, 32 mma per kt
#pragma unroll
        for (int kt = 0; kt < 2; kt++) {
            const float* Ab = &As[cur][kt * KT_STRIDE];
            const float* Bb = &Bs[cur][kt * KT_STRIDE];
            uint32_t a[4][4];
#pragma unroll
            for (int mi = 0; mi < 4; mi++) {
                const int mt = wm * 4 + mi;
                float4 f = *reinterpret_cast<const float4*>(Ab + mt * 128 + lane * 4);
                a[mi][0] = __float_as_uint(f.x);
                a[mi][1] = __float_as_uint(f.y);
                a[mi][2] = __float_as_uint(f.z);
                a[mi][3] = __float_as_uint(f.w);
            }
            uint32_t b[8][2];
#pragma unroll
            for (int ni = 0; ni < 8; ni++) {
                const int nt = wn * 8 + ni;
                float2 f = *reinterpret_cast<const float2*>(Bb + nt * 64 + lane * 2);
                b[ni][0] = __float_as_uint(f.x);
                b[ni][1] = __float_as_uint(f.y);
            }
#pragma unroll
            for (int mi = 0; mi < 4; mi++)
#pragma unroll
                for (int ni = 0; ni < 8; ni++)
                    mma_16x8x8(acc[mi][ni], a[mi], b[ni]);
        }

        // ---- store prefetched tile into other buffer, single barrier
        if (it + 1 < T) {
            const int nx = cur ^ 1;
#pragma unroll
            for (int i = 0; i < 4; i++) {
                const float* af = &av[i].x;
                const float* bf = &bv[i].x;
#pragma unroll
                for (int j = 0; j < 4; j++) {
                    As[nx][aw[i] + 4 * j] = __uint_as_float(f2tf32(af[j]));
                    Bs[nx][bw[i] + 2 * j] = __uint_as_float(f2tf32(bf[j]));
                }
            }
            __syncthreads();
        }
    }

    // ---- epilogue: c0/c1 -> row g, cols 2tg/2tg+1; c2/c3 -> row g+8
#pragma unroll
    for (int mi = 0; mi < 4; mi++) {
#pragma unroll
        for (int half = 0; half < 2; half++) {
            const long row = m0 + wm * 64 + mi * 16 + g + half * 8;
#pragma unroll
            for (int ni = 0; ni < 8; ni++) {
                const int col = n0 + wn * 64 + ni * 8 + 2 * tg;
                float2 r;
                r.x = acc[mi][ni][half * 2 + 0] * alpha;
                r.y = acc[mi][ni][half * 2 + 1] * alpha;
                if (BIAS) {
                    float2 b2v = *reinterpret_cast<const float2*>(bias + col);
                    r.x += b2v.x; r.y += b2v.y;
                }
                if (RELU) { r.x = fmaxf(r.x, 0.f); r.y = fmaxf(r.y, 0.f); }
                *reinterpret_cast<float2*>(C + row * (long)N + col) = r;
            }
        }
    }
}

// ---------------------------------------------------------------------------
// 32x32 tiled transpose: out[C,R] = in[R,C]^T. R,C multiples of 32.
// ---------------------------------------------------------------------------
__global__ __launch_bounds__(256)
void transpose32(const float* __restrict__ in, float* __restrict__ out, int R, int C)
{
    __shared__ float t[32][33];
    int c0 = blockIdx.x * 32, r0 = blockIdx.y * 32;
#pragma unroll
    for (int i = 0; i < 32; i += 8)
        t[threadIdx.y + i][threadIdx.x] = in[(long)(r0 + threadIdx.y + i) * C + c0 + threadIdx.x];
    __syncthreads();
#pragma unroll
    for (int i = 0; i < 32; i += 8)
        out[(long)(c0 + threadIdx.y + i) * R + r0 + threadIdx.x] = t[threadIdx.x][threadIdx.y + i];
}

// ---------------------------------------------------------------------------
// LayerNorm D=512
// ---------------------------------------------------------------------------
__global__ __launch_bounds__(128)
void ln512_kernel(const float* __restrict__ X,
                  const float* __restrict__ gam, const float* __restrict__ bet,
                  float* __restrict__ Y, float* __restrict__ res)
{
    long row = blockIdx.x;
    const int t = threadIdx.x;
    float4 v = reinterpret_cast<const float4*>(X + row * 512)[t];

    float s  = v.x + v.y + v.z + v.w;
    float sq = v.x * v.x + v.y * v.y + v.z * v.z + v.w * v.w;
#pragma unroll
    for (int o = 16; o > 0; o >>= 1) {
        s  += __shfl_xor_sync(0xffffffffu, s, o);
        sq += __shfl_xor_sync(0xffffffffu, sq, o);
    }
    __shared__ float sh_s[4], sh_q[4];
    int w = t >> 5, l = t & 31;
    if (l == 0) { sh_s[w] = s; sh_q[w] = sq; }
    __syncthreads();
    s  = sh_s[0] + sh_s[1] + sh_s[2] + sh_s[3];
    sq = sh_q[0] + sh_q[1] + sh_q[2] + sh_q[3];

    float mean = s * (1.f / 512.f);
    float var  = sq * (1.f / 512.f) - mean * mean;
    float rs   = rsqrtf(var + 1e-6f);

    if (res) reinterpret_cast<float4*>(res + row * 512)[t] = v;

    float4 g4 = reinterpret_cast<const float4*>(gam)[t];
    float4 b4 = reinterpret_cast<const float4*>(bet)[t];
    float4 o;
    o.x = (v.x - mean) * rs * g4.x + b4.x;
    o.y = (v.y - mean) * rs * g4.y + b4.y;
    o.z = (v.z - mean) * rs * g4.z + b4.z;
    o.w = (v.w - mean) * rs * g4.w + b4.w;
    reinterpret_cast<float4*>(Y + row * 512)[t] = o;
}

// ---------------------------------------------------------------------------
// Mask + softmax rows of 2048, in place
// ---------------------------------------------------------------------------
__global__ __launch_bounds__(256)
void softmax2048_kernel(float* __restrict__ Scores, const int* __restrict__ mask)
{
    long row = blockIdx.x;
    float* s      = Scores + row * 2048;
    const int* m  = mask   + row * 2048;
    const int t = threadIdx.x;

    float vals[8];
    float mx = -1e30f;
#pragma unroll
    for (int i = 0; i < 8; i++) {
        int c = t + i * 256;
        float x = s[c];
        if (m[c] == 0) x = -1e9f;
        vals[i] = x;
        mx = fmaxf(mx, x);
    }
    __shared__ float sh[8];
#pragma unroll
    for (int o = 16; o > 0; o >>= 1) mx = fmaxf(mx, __shfl_xor_sync(0xffffffffu, mx, o));
    int w = t >> 5, l = t & 31;
    if (l == 0) sh[w] = mx;
    __syncthreads();
    mx = sh[0];
#pragma unroll
    for (int i = 1; i < 8; i++) mx = fmaxf(mx, sh[i]);
    __syncthreads();

    float sum = 0.f;
#pragma unroll
    for (int i = 0; i < 8; i++) {
        vals[i] = __expf(vals[i] - mx);
        sum += vals[i];
    }
#pragma unroll
    for (int o = 16; o > 0; o >>= 1) sum += __shfl_xor_sync(0xffffffffu, sum, o);
    if (l == 0) sh[w] = sum;
    __syncthreads();
    sum = sh[0] + sh[1] + sh[2] + sh[3] + sh[4] + sh[5] + sh[6] + sh[7];

    float inv = 1.f / sum;
#pragma unroll
    for (int i = 0; i < 8; i++) s[t + i * 256] = vals[i] * inv;
}

// ---------------------------------------------------------------------------
// Launch.  Order chosen so ncu (-s 5 -c 1) captures launch #5 = V-proj GEMM.
// ---------------------------------------------------------------------------
extern "C" void kernel_launch(void* const* d_in, const int* in_sizes, int n_in,
                              void* d_out_, int out_size)
{
    const float* q    = (const float*)d_in[0];
    const float* k    = (const float*)d_in[1];
    const float* v    = (const float*)d_in[2];
    const int*   mask = (const int*)  d_in[3];
    const float* Wq   = (const float*)d_in[4];
    const float* bq   = (const float*)d_in[5];
    const float* Wk   = (const float*)d_in[6];
    const float* bk   = (const float*)d_in[7];
    const float* Wv   = (const float*)d_in[8];
    const float* bv   = (const float*)d_in[9];
    const float* gq   = (const float*)d_in[10];
    const float* beq  = (const float*)d_in[11];
    const float* gk   = (const float*)d_in[12];
    const float* bek  = (const float*)d_in[13];
    const float* gv   = (const float*)d_in[14];
    const float* bev  = (const float*)d_in[15];
    const float* W1   = (const float*)d_in[16];
    const float* b1   = (const float*)d_in[17];
    const float* W2   = (const float*)d_in[18];
    const float* b2   = (const float*)d_in[19];
    float* out = (float*)d_out_;

    float *qp, *kp, *vp, *vpT, *wqT, *wkT, *wvT, *w1T, *w2T;
    cudaGetSymbolAddress((void**)&qp,  g_qp);
    cudaGetSymbolAddress((void**)&kp,  g_kp);
    cudaGetSymbolAddress((void**)&vp,  g_vp);
    cudaGetSymbolAddress((void**)&vpT, g_vpT);
    cudaGetSymbolAddress((void**)&wqT, g_wqT);
    cudaGetSymbolAddress((void**)&wkT, g_wkT);
    cudaGetSymbolAddress((void**)&wvT, g_wvT);
    cudaGetSymbolAddress((void**)&w1T, g_w1T);
    cudaGetSymbolAddress((void**)&w2T, g_w2T);
    float* t1 = qp;   // qp dead after scores GEMM
    float* t2 = kp;   // kp dead after scores GEMM

    dim3 tb(32, 8);
    dim3 blk(128);

    // 0-2) QKV weight transposes
    transpose32<<<dim3(DKc/32,  DMc/32), tb>>>(Wq, wqT, DMc, DKc);   // #0
    transpose32<<<dim3(DKc/32,  DMc/32), tb>>>(Wk, wkT, DMc, DKc);   // #1
    transpose32<<<dim3(DVc/32,  DMc/32), tb>>>(Wv, wvT, DMc, DVc);   // #2

    // 3-5) QKV projections (+bias): [16384,1024] @ [1024,512]
    mma_gemm<true, false><<<dim3(DKc/BN, NTc/BM, 1), blk>>>(
        q, wqT, bq, qp, NTc, DKc, DMc, DMc, 0, 0, 0, 1.f);           // #3
    mma_gemm<true, false><<<dim3(DKc/BN, NTc/BM, 1), blk>>>(
        k, wkT, bk, kp, NTc, DKc, DMc, DMc, 0, 0, 0, 1.f);           // #4
    mma_gemm<true, false><<<dim3(DVc/BN, NTc/BM, 1), blk>>>(
        v, wvT, bv, vp, NTc, DVc, DMc, DMc, 0, 0, 0, 1.f);           // #5 <- ncu

    // LayerNorm (in place). q-LN also emits residual.
    ln512_kernel<<<NTc, 128>>>(qp, gq, beq, qp, out + OFF_RES);
    ln512_kernel<<<NTc, 128>>>(kp, gk, bek, kp, nullptr);
    ln512_kernel<<<NTc, 128>>>(vp, gv, bev, vp, nullptr);

    // vp^T for the attn@V B-operand
    transpose32<<<dim3(DVc/32, NTc/32), tb>>>(vp, vpT, NTc, DVc);

    // scores = (qn @ kn^T) / sqrt(dk), batched -> attn region
    mma_gemm<false, false><<<dim3(Sc/BN, Sc/BM, Bc), blk>>>(
        qp, kp, nullptr, out + OFF_ATT, Sc, Sc, DKc, DKc,
        (long)Sc * DKc, (long)Sc * DKc, (long)Sc * Sc, INV_TEMP);

    // mask + softmax in place
    softmax2048_kernel<<<NTc, 256>>>(out + OFF_ATT, mask);

    // MLP weight transposes (first needed below)
    transpose32<<<dim3(DVc/32,  DVc/32), tb>>>(W1, w1T, DVc, DVc);
    transpose32<<<dim3(DOUTc/32, DVc/32), tb>>>(W2, w2T, DVc, DOUTc);

    // out1 = attn @ vn  (Bt = vpT, rows length NTc; batch offset Sc cols)
    mma_gemm<false, false><<<dim3(DVc/BN, Sc/BM, Bc), blk>>>(
        out + OFF_ATT, vpT, nullptr, t1, Sc, DVc, Sc, NTc,
        (long)Sc * Sc, (long)Sc, (long)Sc * DVc, 1.f);

    // h = relu(out1 @ W1 + b1)
    mma_gemm<true, true><<<dim3(DVc/BN, NTc/BM, 1), blk>>>(
        t1, w1T, b1, t2, NTc, DVc, DVc, DVc, 0, 0, 0, 1.f);

    // out = h @ W2 + b2
    mma_gemm<true, false><<<dim3(DOUTc/BN, NTc/BM, 1), blk>>>(
        t2, w2T, b2, out + OFF_OUT, NTc, DOUTc, DVc, DVc, 0, 0, 0, 1.f);
}

// round 12
// speedup vs baseline: 3.7147x; 1.2784x over previous
#include <cuda_runtime.h>
#include <math.h>
#include <stdint.h>

// ---------------------------------------------------------------------------
// Problem constants
// ---------------------------------------------------------------------------
#define Bc    8
#define Sc    2048
#define DMc   1024
#define DKc   512
#define DVc   512
#define DOUTc 1024
#define NTc   (Bc * Sc)              // 16384 tokens

static const long OFF_OUT = 0L;
static const long OFF_RES = (long)NTc * DOUTc;                   // 16777216
static const long OFF_ATT = OFF_RES + (long)NTc * DKc;           // 25165824

#define INV_TEMP 0.04419417382415922f   // 1/sqrt(512)

// ---------------------------------------------------------------------------
// Scratch (static device globals — no allocation at runtime)
// ---------------------------------------------------------------------------
__device__ __align__(16) float g_qp [(size_t)NTc * DKc];   // qp; later t1 (attn@V out)
__device__ __align__(16) float g_kp [(size_t)NTc * DKc];   // kp; later t2 (MLP hidden)
__device__ __align__(16) float g_vp [(size_t)NTc * DVc];
__device__ __align__(16) float g_vpT[(size_t)DVc * NTc];   // vp^T  [512, 16384]
__device__ __align__(16) float g_wqT[(size_t)DKc * DMc];   // Wq^T  [512, 1024]
__device__ __align__(16) float g_wkT[(size_t)DKc * DMc];
__device__ __align__(16) float g_wvT[(size_t)DVc * DMc];
__device__ __align__(16) float g_w1T[(size_t)DVc * DVc];   // W1^T  [512, 512]
__device__ __align__(16) float g_w2T[(size_t)DOUTc * DVc]; // W2^T  [1024, 512]

// ---------------------------------------------------------------------------
// tf32 helpers (arch-portable: cvt sm_80+, mma.sync m16n8k8 sm_80+, cp.async sm_80+)
// ---------------------------------------------------------------------------
__device__ __forceinline__ uint32_t f2tf32(float f) {
    uint32_t r;
    asm("cvt.rna.tf32.f32 %0, %1;" : "=r"(r) : "f"(f));
    return r;
}
__device__ __forceinline__ float roundtf(float f) { return __uint_as_float(f2tf32(f)); }

__device__ __forceinline__ uint32_t smem_u32(const void* p) {
    uint32_t a;
    asm("{ .reg .u64 t; cvta.to.shared.u64 t, %1; cvt.u32.u64 %0, t; }" : "=r"(a) : "l"(p));
    return a;
}
__device__ __forceinline__ void cp_async16(uint32_t dst, const void* src) {
    asm volatile("cp.async.cg.shared.global [%0], [%1], 16;" :: "r"(dst), "l"(src));
}
#define CP_COMMIT() asm volatile("cp.async.commit_group;" ::: "memory")
#define CP_WAIT0()  asm volatile("cp.async.wait_group 0;" ::: "memory")

__device__ __forceinline__ void ldsm_x4(uint32_t* r, uint32_t addr) {
    asm volatile("ldmatrix.sync.aligned.m8n8.x4.shared.b16 {%0,%1,%2,%3}, [%4];"
                 : "=r"(r[0]), "=r"(r[1]), "=r"(r[2]), "=r"(r[3]) : "r"(addr));
}
__device__ __forceinline__ void mma_16x8x8(float* c, const uint32_t* a, const uint32_t* b) {
    asm volatile(
        "mma.sync.aligned.m16n8k8.row.col.f32.tf32.tf32.f32 "
        "{%0,%1,%2,%3}, {%4,%5,%6,%7}, {%8,%9}, {%0,%1,%2,%3};"
        : "+f"(c[0]), "+f"(c[1]), "+f"(c[2]), "+f"(c[3])
        : "r"(a[0]), "r"(a[1]), "r"(a[2]), "r"(a[3]), "r"(b[0]), "r"(b[1]));
}

// ---------------------------------------------------------------------------
// Smem tiles: plain row-major [128 rows][16 k + 4 pad] fp32 (stride 20 words).
// - cp.async fills 16B chunks (row, k-quad) — no register staging, no STS.
// - ldmatrix.m8n8.x4.b16 loads tf32 fragments: a 16x8 u32 atom viewed as
//   16x16 b16; lane l of each 8x8 b16 matrix holds u32 (row l>>2, col l&3),
//   which IS the mma.sync m16n8k8 operand order.
//   Stride 20: 8 consecutive rows cover word offsets {0,20,8,28,16,4,24,12}
//   (mod 32) -> all 32 banks, conflict-free per ldmatrix phase.
// tf32 rounding is applied by the PRODUCER of each operand (transpose / LN /
// softmax / GEMM epilogue), so smem holds already-rounded values; only raw
// q/k/v inputs need in-register cvt (CVT_A on the QKV GEMMs).
// ---------------------------------------------------------------------------
#define STRIDE 20
#define TILE_WORDS (128 * STRIDE)      // 2560
#define TILE_BYTES (TILE_WORDS * 4)    // 10240

#define BM 128
#define BN 128
#define BK 16

template<bool CVT_A, bool BIAS, bool RELU, bool ROUND_OUT>
__global__ __launch_bounds__(128, 2)
void mma_gemm(const float* __restrict__ A, const float* __restrict__ Bt,
              const float* __restrict__ bias, float* __restrict__ C,
              int M, int N, int K, int ldB,
              long sA, long sB, long sC, float alpha)
{
    A  += (long)blockIdx.z * sA;
    Bt += (long)blockIdx.z * sB;
    C  += (long)blockIdx.z * sC;

    __shared__ __align__(16) float As[2][TILE_WORDS];
    __shared__ __align__(16) float Bs[2][TILE_WORDS];

    const int tid  = threadIdx.x;
    const int wid  = tid >> 5;       // 0..3
    const int lane = tid & 31;
    const int g    = lane >> 2;
    const int tg   = lane & 3;
    const int wm   = (wid & 1);      // warp m index, 64 rows
    const int wn   = (wid >> 1);     // warp n index, 64 cols
    const int m0   = blockIdx.y * BM;
    const int n0   = blockIdx.x * BN;

    const uint32_t sAu = smem_u32(As);
    const uint32_t sBu = smem_u32(Bs);

    // loader: 512 chunks (128 rows x 4 k-quads) per tile, 4 per thread
    int rowc[4];
#pragma unroll
    for (int i = 0; i < 4; i++) rowc[i] = (i * 128 + tid) >> 2;
    const int qc = (tid & 3) * 4;                 // k-quad offset (floats)

    // ldmatrix per-lane base addresses (bytes), group = lane>>3
    const int grp = lane >> 3;
    const uint32_t aAddr0 = sAu + (uint32_t)(((wm * 64 + (grp & 1) * 8 + (lane & 7)) * STRIDE
                                              + (grp >> 1) * 4) * 4);
    const uint32_t bAddr0 = sBu + (uint32_t)(((wn * 64 + (grp >> 1) * 8 + (lane & 7)) * STRIDE
                                              + (grp & 1) * 4) * 4);

    float acc[4][8][4];
#pragma unroll
    for (int i = 0; i < 4; i++)
#pragma unroll
        for (int j = 0; j < 8; j++)
#pragma unroll
            for (int r = 0; r < 4; r++) acc[i][j][r] = 0.f;

    // ---- prologue: async-load tile 0
#pragma unroll
    for (int i = 0; i < 4; i++) {
        uint32_t d = (uint32_t)(rowc[i] * (STRIDE * 4) + qc * 4);
        cp_async16(sAu + d, A  + (long)(m0 + rowc[i]) * K   + qc);
        cp_async16(sBu + d, Bt + (long)(n0 + rowc[i]) * ldB + qc);
    }
    CP_COMMIT();

    const int T = K / BK;
    for (int it = 0; it < T; it++) {
        const int cur = it & 1;

        CP_WAIT0();
        __syncthreads();   // tile `it` visible to all; prior compute on nx done

        // ---- issue next tile into the other buffer (overlaps compute below)
        if (it + 1 < T) {
            const int nx = cur ^ 1;
            const int kc = (it + 1) * BK;
#pragma unroll
            for (int i = 0; i < 4; i++) {
                uint32_t d = (uint32_t)(nx * TILE_BYTES + rowc[i] * (STRIDE * 4) + qc * 4);
                cp_async16(sAu + d, A  + (long)(m0 + rowc[i]) * K   + kc + qc);
                cp_async16(sBu + d, Bt + (long)(n0 + rowc[i]) * ldB + kc + qc);
            }
            CP_COMMIT();
        }

        // ---- compute on buffer cur: 2 k8-steps
        const uint32_t bufOff = (uint32_t)(cur * TILE_BYTES);
#pragma unroll
        for (int kt = 0; kt < 2; kt++) {
            const uint32_t kOff = bufOff + kt * 32;   // 8 floats = 32B
            uint32_t a[4][4];
#pragma unroll
            for (int mi = 0; mi < 4; mi++) {
                ldsm_x4(a[mi], aAddr0 + kOff + mi * (16 * STRIDE * 4));
                if (CVT_A) {
#pragma unroll
                    for (int r = 0; r < 4; r++) a[mi][r] = f2tf32(__uint_as_float(a[mi][r]));
                }
            }
            uint32_t b[4][4];   // [pair p][b0(2p), b1(2p), b0(2p+1), b1(2p+1)]
#pragma unroll
            for (int p = 0; p < 4; p++)
                ldsm_x4(b[p], bAddr0 + kOff + p * (16 * STRIDE * 4));
#pragma unroll
            for (int mi = 0; mi < 4; mi++)
#pragma unroll
                for (int ni = 0; ni < 8; ni++)
                    mma_16x8x8(acc[mi][ni], a[mi], &b[ni >> 1][(ni & 1) * 2]);
        }
    }

    // ---- epilogue: c0/c1 -> row g, cols 2tg/2tg+1; c2/c3 -> row g+8
#pragma unroll
    for (int mi = 0; mi < 4; mi++) {
#pragma unroll
        for (int half = 0; half < 2; half++) {
            const long row = m0 + wm * 64 + mi * 16 + g + half * 8;
#pragma unroll
            for (int ni = 0; ni < 8; ni++) {
                const int col = n0 + wn * 64 + ni * 8 + 2 * tg;
                float2 r;
                r.x = acc[mi][ni][half * 2 + 0] * alpha;
                r.y = acc[mi][ni][half * 2 + 1] * alpha;
                if (BIAS) {
                    float2 b2v = *reinterpret_cast<const float2*>(bias + col);
                    r.x += b2v.x; r.y += b2v.y;
                }
                if (RELU) { r.x = fmaxf(r.x, 0.f); r.y = fmaxf(r.y, 0.f); }
                if (ROUND_OUT) { r.x = roundtf(r.x); r.y = roundtf(r.y); }
                *reinterpret_cast<float2*>(C + row * (long)N + col) = r;
            }
        }
    }
}

// ---------------------------------------------------------------------------
// 32x32 tiled transpose + tf32 rounding: out[C,R] = round(in[R,C]^T)
// ---------------------------------------------------------------------------
__global__ __launch_bounds__(256)
void transpose32(const float* __restrict__ in, float* __restrict__ out, int R, int C)
{
    __shared__ float t[32][33];
    int c0 = blockIdx.x * 32, r0 = blockIdx.y * 32;
#pragma unroll
    for (int i = 0; i < 32; i += 8)
        t[threadIdx.y + i][threadIdx.x] = in[(long)(r0 + threadIdx.y + i) * C + c0 + threadIdx.x];
    __syncthreads();
#pragma unroll
    for (int i = 0; i < 32; i += 8)
        out[(long)(c0 + threadIdx.y + i) * R + r0 + threadIdx.x] =
            roundtf(t[threadIdx.x][threadIdx.y + i]);
}

// ---------------------------------------------------------------------------
// LayerNorm D=512; normalized output rounded to tf32 (GEMM operand),
// residual copy stays raw fp32.
// ---------------------------------------------------------------------------
__global__ __launch_bounds__(128)
void ln512_kernel(const float* __restrict__ X,
                  const float* __restrict__ gam, const float* __restrict__ bet,
                  float* __restrict__ Y, float* __restrict__ res)
{
    long row = blockIdx.x;
    const int t = threadIdx.x;
    float4 v = reinterpret_cast<const float4*>(X + row * 512)[t];

    float s  = v.x + v.y + v.z + v.w;
    float sq = v.x * v.x + v.y * v.y + v.z * v.z + v.w * v.w;
#pragma unroll
    for (int o = 16; o > 0; o >>= 1) {
        s  += __shfl_xor_sync(0xffffffffu, s, o);
        sq += __shfl_xor_sync(0xffffffffu, sq, o);
    }
    __shared__ float sh_s[4], sh_q[4];
    int w = t >> 5, l = t & 31;
    if (l == 0) { sh_s[w] = s; sh_q[w] = sq; }
    __syncthreads();
    s  = sh_s[0] + sh_s[1] + sh_s[2] + sh_s[3];
    sq = sh_q[0] + sh_q[1] + sh_q[2] + sh_q[3];

    float mean = s * (1.f / 512.f);
    float var  = sq * (1.f / 512.f) - mean * mean;
    float rs   = rsqrtf(var + 1e-6f);

    if (res) reinterpret_cast<float4*>(res + row * 512)[t] = v;

    float4 g4 = reinterpret_cast<const float4*>(gam)[t];
    float4 b4 = reinterpret_cast<const float4*>(bet)[t];
    float4 o;
    o.x = roundtf((v.x - mean) * rs * g4.x + b4.x);
    o.y = roundtf((v.y - mean) * rs * g4.y + b4.y);
    o.z = roundtf((v.z - mean) * rs * g4.z + b4.z);
    o.w = roundtf((v.w - mean) * rs * g4.w + b4.w);
    reinterpret_cast<float4*>(Y + row * 512)[t] = o;
}

// ---------------------------------------------------------------------------
// Mask + softmax rows of 2048, in place; output rounded to tf32 (GEMM operand
// for attn@V; also a final output — 1.2e-4 rounding ≪ 1e-3 tolerance).
// ---------------------------------------------------------------------------
__global__ __launch_bounds__(256)
void softmax2048_kernel(float* __restrict__ Scores, const int* __restrict__ mask)
{
    long row = blockIdx.x;
    float* s      = Scores + row * 2048;
    const int* m  = mask   + row * 2048;
    const int t = threadIdx.x;

    float vals[8];
    float mx = -1e30f;
#pragma unroll
    for (int i = 0; i < 8; i++) {
        int c = t + i * 256;
        float x = s[c];
        if (m[c] == 0) x = -1e9f;
        vals[i] = x;
        mx = fmaxf(mx, x);
    }
    __shared__ float sh[8];
#pragma unroll
    for (int o = 16; o > 0; o >>= 1) mx = fmaxf(mx, __shfl_xor_sync(0xffffffffu, mx, o));
    int w = t >> 5, l = t & 31;
    if (l == 0) sh[w] = mx;
    __syncthreads();
    mx = sh[0];
#pragma unroll
    for (int i = 1; i < 8; i++) mx = fmaxf(mx, sh[i]);
    __syncthreads();

    float sum = 0.f;
#pragma unroll
    for (int i = 0; i < 8; i++) {
        vals[i] = __expf(vals[i] - mx);
        sum += vals[i];
    }
#pragma unroll
    for (int o = 16; o > 0; o >>= 1) sum += __shfl_xor_sync(0xffffffffu, sum, o);
    if (l == 0) sh[w] = sum;
    __syncthreads();
    sum = sh[0] + sh[1] + sh[2] + sh[3] + sh[4] + sh[5] + sh[6] + sh[7];

    float inv = 1.f / sum;
#pragma unroll
    for (int i = 0; i < 8; i++) s[t + i * 256] = roundtf(vals[i] * inv);
}

// ---------------------------------------------------------------------------
// Launch.  Order keeps ncu (-s 5 -c 1) on launch #5 = V-proj GEMM.
// ---------------------------------------------------------------------------
extern "C" void kernel_launch(void* const* d_in, const int* in_sizes, int n_in,
                              void* d_out_, int out_size)
{
    const float* q    = (const float*)d_in[0];
    const float* k    = (const float*)d_in[1];
    const float* v    = (const float*)d_in[2];
    const int*   mask = (const int*)  d_in[3];
    const float* Wq   = (const float*)d_in[4];
    const float* bq   = (const float*)d_in[5];
    const float* Wk   = (const float*)d_in[6];
    const float* bk   = (const float*)d_in[7];
    const float* Wv   = (const float*)d_in[8];
    const float* bv   = (const float*)d_in[9];
    const float* gq   = (const float*)d_in[10];
    const float* beq  = (const float*)d_in[11];
    const float* gk   = (const float*)d_in[12];
    const float* bek  = (const float*)d_in[13];
    const float* gv   = (const float*)d_in[14];
    const float* bev  = (const float*)d_in[15];
    const float* W1   = (const float*)d_in[16];
    const float* b1   = (const float*)d_in[17];
    const float* W2   = (const float*)d_in[18];
    const float* b2   = (const float*)d_in[19];
    float* out = (float*)d_out_;

    float *qp, *kp, *vp, *vpT, *wqT, *wkT, *wvT, *w1T, *w2T;
    cudaGetSymbolAddress((void**)&qp,  g_qp);
    cudaGetSymbolAddress((void**)&kp,  g_kp);
    cudaGetSymbolAddress((void**)&vp,  g_vp);
    cudaGetSymbolAddress((void**)&vpT, g_vpT);
    cudaGetSymbolAddress((void**)&wqT, g_wqT);
    cudaGetSymbolAddress((void**)&wkT, g_wkT);
    cudaGetSymbolAddress((void**)&wvT, g_wvT);
    cudaGetSymbolAddress((void**)&w1T, g_w1T);
    cudaGetSymbolAddress((void**)&w2T, g_w2T);
    float* t1 = qp;   // qp dead after scores GEMM
    float* t2 = kp;   // kp dead after scores GEMM

    dim3 tb(32, 8);
    dim3 blk(128);

    // 0-2) QKV weight transposes (rounded to tf32)
    transpose32<<<dim3(DKc/32,  DMc/32), tb>>>(Wq, wqT, DMc, DKc);   // #0
    transpose32<<<dim3(DKc/32,  DMc/32), tb>>>(Wk, wkT, DMc, DKc);   // #1
    transpose32<<<dim3(DVc/32,  DMc/32), tb>>>(Wv, wvT, DMc, DVc);   // #2

    // 3-5) QKV projections (+bias); A = raw inputs -> CVT_A
    mma_gemm<true, true, false, false><<<dim3(DKc/BN, NTc/BM, 1), blk>>>(
        q, wqT, bq, qp, NTc, DKc, DMc, DMc, 0, 0, 0, 1.f);           // #3
    mma_gemm<true, true, false, false><<<dim3(DKc/BN, NTc/BM, 1), blk>>>(
        k, wkT, bk, kp, NTc, DKc, DMc, DMc, 0, 0, 0, 1.f);           // #4
    mma_gemm<true, true, false, false><<<dim3(DVc/BN, NTc/BM, 1), blk>>>(
        v, wvT, bv, vp, NTc, DVc, DMc, DMc, 0, 0, 0, 1.f);           // #5 <- ncu

    // LayerNorm (in place, rounded). q-LN also emits raw residual.
    ln512_kernel<<<NTc, 128>>>(qp, gq, beq, qp, out + OFF_RES);
    ln512_kernel<<<NTc, 128>>>(kp, gk, bek, kp, nullptr);
    ln512_kernel<<<NTc, 128>>>(vp, gv, bev, vp, nullptr);

    // vp^T for the attn@V B-operand (rounded; idempotent)
    transpose32<<<dim3(DVc/32, NTc/32), tb>>>(vp, vpT, NTc, DVc);

    // scores = (qn @ kn^T) / sqrt(dk); operands pre-rounded
    mma_gemm<false, false, false, false><<<dim3(Sc/BN, Sc/BM, Bc), blk>>>(
        qp, kp, nullptr, out + OFF_ATT, Sc, Sc, DKc, DKc,
        (long)Sc * DKc, (long)Sc * DKc, (long)Sc * Sc, INV_TEMP);

    // mask + softmax in place (rounded output)
    softmax2048_kernel<<<NTc, 256>>>(out + OFF_ATT, mask);

    // MLP weight transposes (rounded)
    transpose32<<<dim3(DVc/32,  DVc/32), tb>>>(W1, w1T, DVc, DVc);
    transpose32<<<dim3(DOUTc/32, DVc/32), tb>>>(W2, w2T, DVc, DOUTc);

    // out1 = attn @ vn; round output (feeds MLP1 as A)
    mma_gemm<false, false, false, true><<<dim3(DVc/BN, Sc/BM, Bc), blk>>>(
        out + OFF_ATT, vpT, nullptr, t1, Sc, DVc, Sc, NTc,
        (long)Sc * Sc, (long)Sc, (long)Sc * DVc, 1.f);

    // h = relu(out1 @ W1 + b1); round output (feeds MLP2 as A)
    mma_gemm<false, true, true, true><<<dim3(DVc/BN, NTc/BM, 1), blk>>>(
        t1, w1T, b1, t2, NTc, DVc, DVc, DVc, 0, 0, 0, 1.f);

    // out = h @ W2 + b2 (final, raw fp32)
    mma_gemm<false, true, false, false><<<dim3(DOUTc/BN, NTc/BM, 1), blk>>>(
        t2, w2T, b2, out + OFF_OUT, NTc, DOUTc, DVc, DVc, 0, 0, 0, 1.f);
}

// round 13
// speedup vs baseline: 3.9174x; 1.0546x over previous
#include <cuda_runtime.h>
#include <math.h>
#include <stdint.h>

// ---------------------------------------------------------------------------
// Problem constants
// ---------------------------------------------------------------------------
#define Bc    8
#define Sc    2048
#define DMc   1024
#define DKc   512
#define DVc   512
#define DOUTc 1024
#define NTc   (Bc * Sc)              // 16384 tokens

static const long OFF_OUT = 0L;
static const long OFF_RES = (long)NTc * DOUTc;                   // 16777216
static const long OFF_ATT = OFF_RES + (long)NTc * DKc;           // 25165824

#define INV_TEMP 0.04419417382415922f   // 1/sqrt(512)

// ---------------------------------------------------------------------------
// Scratch (static device globals — no allocation at runtime)
// ---------------------------------------------------------------------------
__device__ __align__(16) float g_qp [(size_t)NTc * DKc];   // qp; later t1 (attn@V out)
__device__ __align__(16) float g_kp [(size_t)NTc * DKc];   // kp; later t2 (MLP hidden)
__device__ __align__(16) float g_vp [(size_t)NTc * DVc];
__device__ __align__(16) float g_vpT[(size_t)DVc * NTc];   // vp^T  [512, 16384]
__device__ __align__(16) float g_wqT[(size_t)DKc * DMc];   // Wq^T  [512, 1024]
__device__ __align__(16) float g_wkT[(size_t)DKc * DMc];
__device__ __align__(16) float g_wvT[(size_t)DVc * DMc];
__device__ __align__(16) float g_w1T[(size_t)DVc * DVc];   // W1^T  [512, 512]
__device__ __align__(16) float g_w2T[(size_t)DOUTc * DVc]; // W2^T  [1024, 512]

// ---------------------------------------------------------------------------
// tf32 helpers (arch-portable: cvt sm_80+, mma.sync m16n8k8 sm_80+, cp.async sm_80+)
// ---------------------------------------------------------------------------
__device__ __forceinline__ uint32_t f2tf32(float f) {
    uint32_t r;
    asm("cvt.rna.tf32.f32 %0, %1;" : "=r"(r) : "f"(f));
    return r;
}
__device__ __forceinline__ float roundtf(float f) { return __uint_as_float(f2tf32(f)); }

__device__ __forceinline__ uint32_t smem_u32(const void* p) {
    uint32_t a;
    asm("{ .reg .u64 t; cvta.to.shared.u64 t, %1; cvt.u32.u64 %0, t; }" : "=r"(a) : "l"(p));
    return a;
}
__device__ __forceinline__ void cp_async16(uint32_t dst, const void* src) {
    asm volatile("cp.async.cg.shared.global [%0], [%1], 16;" :: "r"(dst), "l"(src));
}
#define CP_COMMIT() asm volatile("cp.async.commit_group;" ::: "memory")
#define CP_WAIT1()  asm volatile("cp.async.wait_group 1;" ::: "memory")

__device__ __forceinline__ void ldsm_x4(uint32_t* r, uint32_t addr) {
    asm volatile("ldmatrix.sync.aligned.m8n8.x4.shared.b16 {%0,%1,%2,%3}, [%4];"
                 : "=r"(r[0]), "=r"(r[1]), "=r"(r[2]), "=r"(r[3]) : "r"(addr));
}
__device__ __forceinline__ void mma_16x8x8(float* c, const uint32_t* a, const uint32_t* b) {
    asm volatile(
        "mma.sync.aligned.m16n8k8.row.col.f32.tf32.tf32.f32 "
        "{%0,%1,%2,%3}, {%4,%5,%6,%7}, {%8,%9}, {%0,%1,%2,%3};"
        : "+f"(c[0]), "+f"(c[1]), "+f"(c[2]), "+f"(c[3])
        : "r"(a[0]), "r"(a[1]), "r"(a[2]), "r"(a[3]), "r"(b[0]), "r"(b[1]));
}

// ---------------------------------------------------------------------------
// Smem tiles: row-major [128 rows][32 k + 4 pad] fp32 (stride 36 words).
// 3-stage cp.async pipeline (wait_group 1 => 2-stage lookahead), BK=32.
// Stride 36: 8 consecutive rows cover word offsets 4r mod 32 = {0,4,...,28},
// each ldmatrix phase (8 rows x 16B) spans all 32 banks -> conflict-free;
// cp.async 16B fills are trivially conflict-free.
// tf32 rounding applied by the PRODUCER of each operand (transpose / LN /
// softmax / GEMM epilogue); only raw q/k/v need in-register cvt (CVT_A).
// ---------------------------------------------------------------------------
#define STRIDE 36
#define TILE_WORDS (128 * STRIDE)      // 4608
#define TILE_BYTES (TILE_WORDS * 4)    // 18432
#define NSTAGE 3
#define SMEM_DYN (NSTAGE * 2 * TILE_BYTES)   // 110592

#define BM 128
#define BN 128
#define BK 32

template<bool CVT_A, bool BIAS, bool RELU, bool ROUND_OUT>
__global__ __launch_bounds__(128, 2)
void mma_gemm(const float* __restrict__ A, const float* __restrict__ Bt,
              const float* __restrict__ bias, float* __restrict__ C,
              int M, int N, int K, int ldB,
              long sA, long sB, long sC, float alpha)
{
    extern __shared__ __align__(16) float smem[];

    A  += (long)blockIdx.z * sA;
    Bt += (long)blockIdx.z * sB;
    C  += (long)blockIdx.z * sC;

    const int tid  = threadIdx.x;
    const int wid  = tid >> 5;       // 0..3
    const int lane = tid & 31;
    const int g    = lane >> 2;
    const int tg   = lane & 3;
    const int wm   = (wid & 1);      // warp m index, 64 rows
    const int wn   = (wid >> 1);     // warp n index, 64 cols
    const int m0   = blockIdx.y * BM;
    const int n0   = blockIdx.x * BN;

    const uint32_t sAu = smem_u32(smem);                       // A stages [0..2]
    const uint32_t sBu = sAu + NSTAGE * TILE_BYTES;            // B stages [0..2]

    // loader: 1024 chunks (128 rows x 8 k-quads) per tile, 8 per thread
    int rowc[8];
#pragma unroll
    for (int i = 0; i < 8; i++) rowc[i] = (i * 128 + tid) >> 3;
    const int qc = (tid & 7) * 4;                 // k-quad float offset (0..28)

    // ldmatrix per-lane base addresses (bytes), group = lane>>3
    const int grp = lane >> 3;
    const uint32_t aAddr0 = sAu + (uint32_t)(((wm * 64 + (grp & 1) * 8 + (lane & 7)) * STRIDE
                                              + (grp >> 1) * 4) * 4);
    const uint32_t bAddr0 = sBu + (uint32_t)(((wn * 64 + (grp >> 1) * 8 + (lane & 7)) * STRIDE
                                              + (grp & 1) * 4) * 4);

    float acc[4][8][4];
#pragma unroll
    for (int i = 0; i < 4; i++)
#pragma unroll
        for (int j = 0; j < 8; j++)
#pragma unroll
            for (int r = 0; r < 4; r++) acc[i][j][r] = 0.f;

    const int T = K / BK;

    // ---- prologue: issue stages 0 and 1
#pragma unroll
    for (int s = 0; s < 2; s++) {
        if (s < T) {
            const int kc = s * BK;
            const uint32_t so = (uint32_t)(s * TILE_BYTES);
#pragma unroll
            for (int i = 0; i < 8; i++) {
                uint32_t d = so + (uint32_t)(rowc[i] * (STRIDE * 4) + qc * 4);
                cp_async16(sAu + d, A  + (long)(m0 + rowc[i]) * K   + kc + qc);
                cp_async16(sBu + d, Bt + (long)(n0 + rowc[i]) * ldB + kc + qc);
            }
        }
        CP_COMMIT();
    }

    int cur = 0;
    for (int it = 0; it < T; it++) {
        CP_WAIT1();        // stage `it` complete (<=1 group pending)
        __syncthreads();   // all warps done with the buffer we are about to refill

        // ---- issue stage it+2 into buffer (cur+2)%3 ; ALWAYS commit (tail-safe)
        if (it + 2 < T) {
            int ib = cur + 2; if (ib >= NSTAGE) ib -= NSTAGE;
            const int kc = (it + 2) * BK;
            const uint32_t so = (uint32_t)(ib * TILE_BYTES);
#pragma unroll
            for (int i = 0; i < 8; i++) {
                uint32_t d = so + (uint32_t)(rowc[i] * (STRIDE * 4) + qc * 4);
                cp_async16(sAu + d, A  + (long)(m0 + rowc[i]) * K   + kc + qc);
                cp_async16(sBu + d, Bt + (long)(n0 + rowc[i]) * ldB + kc + qc);
            }
        }
        CP_COMMIT();

        // ---- compute on buffer cur: 4 k8-steps
        const uint32_t bufOff = (uint32_t)(cur * TILE_BYTES);
#pragma unroll
        for (int kt = 0; kt < 4; kt++) {
            const uint32_t kOff = bufOff + kt * 32;   // 8 floats = 32B
            uint32_t a[4][4];
#pragma unroll
            for (int mi = 0; mi < 4; mi++) {
                ldsm_x4(a[mi], aAddr0 + kOff + mi * (16 * STRIDE * 4));
                if (CVT_A) {
#pragma unroll
                    for (int r = 0; r < 4; r++) a[mi][r] = f2tf32(__uint_as_float(a[mi][r]));
                }
            }
            uint32_t b[4][4];
#pragma unroll
            for (int p = 0; p < 4; p++)
                ldsm_x4(b[p], bAddr0 + kOff + p * (16 * STRIDE * 4));
#pragma unroll
            for (int mi = 0; mi < 4; mi++)
#pragma unroll
                for (int ni = 0; ni < 8; ni++)
                    mma_16x8x8(acc[mi][ni], a[mi], &b[ni >> 1][(ni & 1) * 2]);
        }

        if (++cur == NSTAGE) cur = 0;
    }

    // ---- epilogue: c0/c1 -> row g, cols 2tg/2tg+1; c2/c3 -> row g+8
#pragma unroll
    for (int mi = 0; mi < 4; mi++) {
#pragma unroll
        for (int half = 0; half < 2; half++) {
            const long row = m0 + wm * 64 + mi * 16 + g + half * 8;
#pragma unroll
            for (int ni = 0; ni < 8; ni++) {
                const int col = n0 + wn * 64 + ni * 8 + 2 * tg;
                float2 r;
                r.x = acc[mi][ni][half * 2 + 0] * alpha;
                r.y = acc[mi][ni][half * 2 + 1] * alpha;
                if (BIAS) {
                    float2 b2v = *reinterpret_cast<const float2*>(bias + col);
                    r.x += b2v.x; r.y += b2v.y;
                }
                if (RELU) { r.x = fmaxf(r.x, 0.f); r.y = fmaxf(r.y, 0.f); }
                if (ROUND_OUT) { r.x = roundtf(r.x); r.y = roundtf(r.y); }
                *reinterpret_cast<float2*>(C + row * (long)N + col) = r;
            }
        }
    }
}

// ---------------------------------------------------------------------------
// 32x32 tiled transpose + tf32 rounding: out[C,R] = round(in[R,C]^T)
// ---------------------------------------------------------------------------
__global__ __launch_bounds__(256)
void transpose32(const float* __restrict__ in, float* __restrict__ out, int R, int C)
{
    __shared__ float t[32][33];
    int c0 = blockIdx.x * 32, r0 = blockIdx.y * 32;
#pragma unroll
    for (int i = 0; i < 32; i += 8)
        t[threadIdx.y + i][threadIdx.x] = in[(long)(r0 + threadIdx.y + i) * C + c0 + threadIdx.x];
    __syncthreads();
#pragma unroll
    for (int i = 0; i < 32; i += 8)
        out[(long)(c0 + threadIdx.y + i) * R + r0 + threadIdx.x] =
            roundtf(t[threadIdx.x][threadIdx.y + i]);
}

// ---------------------------------------------------------------------------
// LayerNorm D=512; normalized output rounded to tf32 (GEMM operand),
// residual copy stays raw fp32.
// ---------------------------------------------------------------------------
__global__ __launch_bounds__(128)
void ln512_kernel(const float* __restrict__ X,
                  const float* __restrict__ gam, const float* __restrict__ bet,
                  float* __restrict__ Y, float* __restrict__ res)
{
    long row = blockIdx.x;
    const int t = threadIdx.x;
    float4 v = reinterpret_cast<const float4*>(X + row * 512)[t];

    float s  = v.x + v.y + v.z + v.w;
    float sq = v.x * v.x + v.y * v.y + v.z * v.z + v.w * v.w;
#pragma unroll
    for (int o = 16; o > 0; o >>= 1) {
        s  += __shfl_xor_sync(0xffffffffu, s, o);
        sq += __shfl_xor_sync(0xffffffffu, sq, o);
    }
    __shared__ float sh_s[4], sh_q[4];
    int w = t >> 5, l = t & 31;
    if (l == 0) { sh_s[w] = s; sh_q[w] = sq; }
    __syncthreads();
    s  = sh_s[0] + sh_s[1] + sh_s[2] + sh_s[3];
    sq = sh_q[0] + sh_q[1] + sh_q[2] + sh_q[3];

    float mean = s * (1.f / 512.f);
    float var  = sq * (1.f / 512.f) - mean * mean;
    float rs   = rsqrtf(var + 1e-6f);

    if (res) reinterpret_cast<float4*>(res + row * 512)[t] = v;

    float4 g4 = reinterpret_cast<const float4*>(gam)[t];
    float4 b4 = reinterpret_cast<const float4*>(bet)[t];
    float4 o;
    o.x = roundtf((v.x - mean) * rs * g4.x + b4.x);
    o.y = roundtf((v.y - mean) * rs * g4.y + b4.y);
    o.z = roundtf((v.z - mean) * rs * g4.z + b4.z);
    o.w = roundtf((v.w - mean) * rs * g4.w + b4.w);
    reinterpret_cast<float4*>(Y + row * 512)[t] = o;
}

// ---------------------------------------------------------------------------
// Mask + softmax rows of 2048, in place; output rounded to tf32.
// ---------------------------------------------------------------------------
__global__ __launch_bounds__(256)
void softmax2048_kernel(float* __restrict__ Scores, const int* __restrict__ mask)
{
    long row = blockIdx.x;
    float* s      = Scores + row * 2048;
    const int* m  = mask   + row * 2048;
    const int t = threadIdx.x;

    float vals[8];
    float mx = -1e30f;
#pragma unroll
    for (int i = 0; i < 8; i++) {
        int c = t + i * 256;
        float x = s[c];
        if (m[c] == 0) x = -1e9f;
        vals[i] = x;
        mx = fmaxf(mx, x);
    }
    __shared__ float sh[8];
#pragma unroll
    for (int o = 16; o > 0; o >>= 1) mx = fmaxf(mx, __shfl_xor_sync(0xffffffffu, mx, o));
    int w = t >> 5, l = t & 31;
    if (l == 0) sh[w] = mx;
    __syncthreads();
    mx = sh[0];
#pragma unroll
    for (int i = 1; i < 8; i++) mx = fmaxf(mx, sh[i]);
    __syncthreads();

    float sum = 0.f;
#pragma unroll
    for (int i = 0; i < 8; i++) {
        vals[i] = __expf(vals[i] - mx);
        sum += vals[i];
    }
#pragma unroll
    for (int o = 16; o > 0; o >>= 1) sum += __shfl_xor_sync(0xffffffffu, sum, o);
    if (l == 0) sh[w] = sum;
    __syncthreads();
    sum = sh[0] + sh[1] + sh[2] + sh[3] + sh[4] + sh[5] + sh[6] + sh[7];

    float inv = 1.f / sum;
#pragma unroll
    for (int i = 0; i < 8; i++) s[t + i * 256] = roundtf(vals[i] * inv);
}

// ---------------------------------------------------------------------------
// Launch.  Order keeps ncu (-s 5 -c 1) on launch #5 = V-proj GEMM.
// ---------------------------------------------------------------------------
extern "C" void kernel_launch(void* const* d_in, const int* in_sizes, int n_in,
                              void* d_out_, int out_size)
{
    const float* q    = (const float*)d_in[0];
    const float* k    = (const float*)d_in[1];
    const float* v    = (const float*)d_in[2];
    const int*   mask = (const int*)  d_in[3];
    const float* Wq   = (const float*)d_in[4];
    const float* bq   = (const float*)d_in[5];
    const float* Wk   = (const float*)d_in[6];
    const float* bk   = (const float*)d_in[7];
    const float* Wv   = (const float*)d_in[8];
    const float* bv   = (const float*)d_in[9];
    const float* gq   = (const float*)d_in[10];
    const float* beq  = (const float*)d_in[11];
    const float* gk   = (const float*)d_in[12];
    const float* bek  = (const float*)d_in[13];
    const float* gv   = (const float*)d_in[14];
    const float* bev  = (const float*)d_in[15];
    const float* W1   = (const float*)d_in[16];
    const float* b1   = (const float*)d_in[17];
    const float* W2   = (const float*)d_in[18];
    const float* b2   = (const float*)d_in[19];
    float* out = (float*)d_out_;

    float *qp, *kp, *vp, *vpT, *wqT, *wkT, *wvT, *w1T, *w2T;
    cudaGetSymbolAddress((void**)&qp,  g_qp);
    cudaGetSymbolAddress((void**)&kp,  g_kp);
    cudaGetSymbolAddress((void**)&vp,  g_vp);
    cudaGetSymbolAddress((void**)&vpT, g_vpT);
    cudaGetSymbolAddress((void**)&wqT, g_wqT);
    cudaGetSymbolAddress((void**)&wkT, g_wkT);
    cudaGetSymbolAddress((void**)&wvT, g_wvT);
    cudaGetSymbolAddress((void**)&w1T, g_w1T);
    cudaGetSymbolAddress((void**)&w2T, g_w2T);
    float* t1 = qp;   // qp dead after scores GEMM
    float* t2 = kp;   // kp dead after scores GEMM

    // opt-in dynamic smem (110.6 KB/CTA; 2 CTAs/SM fit the 228 KB carveout)
    cudaFuncSetAttribute(mma_gemm<true,  true,  false, false>, cudaFuncAttributeMaxDynamicSharedMemorySize, SMEM_DYN);
    cudaFuncSetAttribute(mma_gemm<false, false, false, false>, cudaFuncAttributeMaxDynamicSharedMemorySize, SMEM_DYN);
    cudaFuncSetAttribute(mma_gemm<false, false, false, true >, cudaFuncAttributeMaxDynamicSharedMemorySize, SMEM_DYN);
    cudaFuncSetAttribute(mma_gemm<false, true,  true,  true >, cudaFuncAttributeMaxDynamicSharedMemorySize, SMEM_DYN);
    cudaFuncSetAttribute(mma_gemm<false, true,  false, false>, cudaFuncAttributeMaxDynamicSharedMemorySize, SMEM_DYN);

    dim3 tb(32, 8);
    dim3 blk(128);

    // 0-2) QKV weight transposes (rounded to tf32)
    transpose32<<<dim3(DKc/32,  DMc/32), tb>>>(Wq, wqT, DMc, DKc);   // #0
    transpose32<<<dim3(DKc/32,  DMc/32), tb>>>(Wk, wkT, DMc, DKc);   // #1
    transpose32<<<dim3(DVc/32,  DMc/32), tb>>>(Wv, wvT, DMc, DVc);   // #2

    // 3-5) QKV projections (+bias); A = raw inputs -> CVT_A
    mma_gemm<true, true, false, false><<<dim3(DKc/BN, NTc/BM, 1), blk, SMEM_DYN>>>(
        q, wqT, bq, qp, NTc, DKc, DMc, DMc, 0, 0, 0, 1.f);           // #3
    mma_gemm<true, true, false, false><<<dim3(DKc/BN, NTc/BM, 1), blk, SMEM_DYN>>>(
        k, wkT, bk, kp, NTc, DKc, DMc, DMc, 0, 0, 0, 1.f);           // #4
    mma_gemm<true, true, false, false><<<dim3(DVc/BN, NTc/BM, 1), blk, SMEM_DYN>>>(
        v, wvT, bv, vp, NTc, DVc, DMc, DMc, 0, 0, 0, 1.f);           // #5 <- ncu

    // LayerNorm (in place, rounded). q-LN also emits raw residual.
    ln512_kernel<<<NTc, 128>>>(qp, gq, beq, qp, out + OFF_RES);
    ln512_kernel<<<NTc, 128>>>(kp, gk, bek, kp, nullptr);
    ln512_kernel<<<NTc, 128>>>(vp, gv, bev, vp, nullptr);

    // vp^T for the attn@V B-operand (rounded; idempotent)
    transpose32<<<dim3(DVc/32, NTc/32), tb>>>(vp, vpT, NTc, DVc);

    // scores = (qn @ kn^T) / sqrt(dk); operands pre-rounded
    mma_gemm<false, false, false, false><<<dim3(Sc/BN, Sc/BM, Bc), blk, SMEM_DYN>>>(
        qp, kp, nullptr, out + OFF_ATT, Sc, Sc, DKc, DKc,
        (long)Sc * DKc, (long)Sc * DKc, (long)Sc * Sc, INV_TEMP);

    // mask + softmax in place (rounded output)
    softmax2048_kernel<<<NTc, 256>>>(out + OFF_ATT, mask);

    // MLP weight transposes (rounded)
    transpose32<<<dim3(DVc/32,  DVc/32), tb>>>(W1, w1T, DVc, DVc);
    transpose32<<<dim3(DOUTc/32, DVc/32), tb>>>(W2, w2T, DVc, DOUTc);

    // out1 = attn @ vn; round output (feeds MLP1 as A)
    mma_gemm<false, false, false, true><<<dim3(DVc/BN, Sc/BM, Bc), blk, SMEM_DYN>>>(
        out + OFF_ATT, vpT, nullptr, t1, Sc, DVc, Sc, NTc,
        (long)Sc * Sc, (long)Sc, (long)Sc * DVc, 1.f);

    // h = relu(out1 @ W1 + b1); round output (feeds MLP2 as A)
    mma_gemm<false, true, true, true><<<dim3(DVc/BN, NTc/BM, 1), blk, SMEM_DYN>>>(
        t1, w1T, b1, t2, NTc, DVc, DVc, DVc, 0, 0, 0, 1.f);

    // out = h @ W2 + b2 (final, raw fp32)
    mma_gemm<false, true, false, false><<<dim3(DOUTc/BN, NTc/BM, 1), blk, SMEM_DYN>>>(
        t2, w2T, b2, out + OFF_OUT, NTc, DOUTc, DVc, DVc, 0, 0, 0, 1.f);
}

// round 14
// speedup vs baseline: 6.5884x; 1.6818x over previous
#include <cuda_runtime.h>
#include <cuda_fp16.h>
#include <math.h>
#include <stdint.h>

// ---------------------------------------------------------------------------
// Problem constants
// ---------------------------------------------------------------------------
#define Bc    8
#define Sc    2048
#define DMc   1024
#define DKc   512
#define DVc   512
#define DOUTc 1024
#define NTc   (Bc * Sc)              // 16384 tokens

static const long OFF_OUT = 0L;
static const long OFF_RES = (long)NTc * DOUTc;                   // 16777216
static const long OFF_ATT = OFF_RES + (long)NTc * DKc;           // 25165824

#define INV_TEMP 0.04419417382415922f   // 1/sqrt(512)

// ---------------------------------------------------------------------------
// Scratch (static device globals — no allocation at runtime)
// fp32: GEMM outputs feeding LN + residual.  fp16: all GEMM operands.
// ---------------------------------------------------------------------------
__device__ __align__(16) float  g_qp [(size_t)NTc * DKc];
__device__ __align__(16) float  g_kp [(size_t)NTc * DKc];
__device__ __align__(16) float  g_vp [(size_t)NTc * DVc];
__device__ __align__(16) __half g_qh [(size_t)NTc * DMc];   // fp16(q)
__device__ __align__(16) __half g_kh [(size_t)NTc * DMc];
__device__ __align__(16) __half g_vh [(size_t)NTc * DMc];
__device__ __align__(16) __half g_qn [(size_t)NTc * DKc];   // LN(q); later t1h
__device__ __align__(16) __half g_kn [(size_t)NTc * DKc];   // LN(k); later t2h
__device__ __align__(16) __half g_vn [(size_t)NTc * DVc];   // LN(v)
__device__ __align__(16) __half g_vpT[(size_t)DVc * NTc];   // LN(v)^T
__device__ __align__(16) __half g_ath[(size_t)NTc * Sc];    // fp16(attn)
__device__ __align__(16) __half g_wqT[(size_t)DKc * DMc];
__device__ __align__(16) __half g_wkT[(size_t)DKc * DMc];
__device__ __align__(16) __half g_wvT[(size_t)DVc * DMc];
__device__ __align__(16) __half g_w1T[(size_t)DVc * DVc];
__device__ __align__(16) __half g_w2T[(size_t)DOUTc * DVc];

// ---------------------------------------------------------------------------
// helpers
// ---------------------------------------------------------------------------
__device__ __forceinline__ uint32_t f2tf32(float f) {
    uint32_t r;
    asm("cvt.rna.tf32.f32 %0, %1;" : "=r"(r) : "f"(f));
    return r;
}
__device__ __forceinline__ float roundtf(float f) { return __uint_as_float(f2tf32(f)); }

__device__ __forceinline__ uint32_t smem_u32(const void* p) {
    uint32_t a;
    asm("{ .reg .u64 t; cvta.to.shared.u64 t, %1; cvt.u32.u64 %0, t; }" : "=r"(a) : "l"(p));
    return a;
}
__device__ __forceinline__ void cp_async16(uint32_t dst, const void* src) {
    asm volatile("cp.async.cg.shared.global [%0], [%1], 16;" :: "r"(dst), "l"(src));
}
#define CP_COMMIT() asm volatile("cp.async.commit_group;" ::: "memory")
#define CP_WAIT1()  asm volatile("cp.async.wait_group 1;" ::: "memory")

__device__ __forceinline__ void ldsm_x4(uint32_t* r, uint32_t addr) {
    asm volatile("ldmatrix.sync.aligned.m8n8.x4.shared.b16 {%0,%1,%2,%3}, [%4];"
                 : "=r"(r[0]), "=r"(r[1]), "=r"(r[2]), "=r"(r[3]) : "r"(addr));
}
// fp16 mma, fp32 accumulate: D[16,8] += A[16,16] * B[16,8] (B col-major = [n][k])
__device__ __forceinline__ void mma_16x8x16(float* c, const uint32_t* a, const uint32_t* b) {
    asm volatile(
        "mma.sync.aligned.m16n8k16.row.col.f32.f16.f16.f32 "
        "{%0,%1,%2,%3}, {%4,%5,%6,%7}, {%8,%9}, {%0,%1,%2,%3};"
        : "+f"(c[0]), "+f"(c[1]), "+f"(c[2]), "+f"(c[3])
        : "r"(a[0]), "r"(a[1]), "r"(a[2]), "r"(a[3]), "r"(b[0]), "r"(b[1]));
}

// ---------------------------------------------------------------------------
// fp16 GEMM: C[M,N] = alpha * A[M,K] @ Bt[N,K]^T (+bias) (+relu)
// A, Bt fp16; C fp32 (OUT_HALF=0) or fp16 (OUT_HALF=1). fp32 accumulate.
// BM=BN=128, BK=32, 128 threads (4 warps, 64x64 warp tiles), 3-stage cp.async
// (wait_group 1). Smem rows: 32 halfs + 8 pad = stride 40 halfs (80B);
// 8 consecutive rows hit word offsets {0,20,8,28,16,4,24,12} -> every
// ldmatrix phase and cp.async fill spans all 32 banks, conflict-free.
// Fragment rule (validated R12/R13): ldmatrix lane l -> row l>>2, word l&3.
// ---------------------------------------------------------------------------
#define STRIDE_H 40
#define TILE_BYTES_H (128 * STRIDE_H * 2)     // 10240
#define NSTAGE 3
#define SMEM_DYN (NSTAGE * 2 * TILE_BYTES_H)  // 61440

#define BM 128
#define BN 128
#define BK 32

template<bool BIAS, bool RELU, bool OUT_HALF>
__global__ __launch_bounds__(128, 2)
void mma_gemm(const __half* __restrict__ A, const __half* __restrict__ Bt,
              const float* __restrict__ bias, void* __restrict__ Cv,
              int M, int N, int K, int ldB,
              long sA, long sB, long sC, float alpha)
{
    extern __shared__ __align__(16) __half smem[];

    A  += (long)blockIdx.z * sA;
    Bt += (long)blockIdx.z * sB;

    const int tid  = threadIdx.x;
    const int wid  = tid >> 5;
    const int lane = tid & 31;
    const int g    = lane >> 2;
    const int tg   = lane & 3;
    const int wm   = (wid & 1);
    const int wn   = (wid >> 1);
    const int m0   = blockIdx.y * BM;
    const int n0   = blockIdx.x * BN;

    const uint32_t sAu = smem_u32(smem);
    const uint32_t sBu = sAu + NSTAGE * TILE_BYTES_H;

    // loader: 512 chunks (128 rows x 4 k-octs of 8 halfs) per tile, 4/thread
    int rowc[4];
#pragma unroll
    for (int i = 0; i < 4; i++) rowc[i] = (i * 128 + tid) >> 2;
    const int koct = (tid & 3) * 8;               // half offset (0,8,16,24)

    // ldmatrix bases (bytes). grp = lane>>3.
    // A x4 matrices: (m0-7,k0-7),(m8-15,k0-7),(m0-7,k8-15),(m8-15,k8-15)
    const int grp = lane >> 3;
    const uint32_t aAddr0 = sAu + (uint32_t)((((wm * 64 + (grp & 1) * 8 + (lane & 7)) * STRIDE_H)
                                              + (grp >> 1) * 8) * 2);
    // B x4 matrices: (n0-7,k0-7),(n0-7,k8-15),(n8-15,k0-7),(n8-15,k8-15)
    const uint32_t bAddr0 = sBu + (uint32_t)((((wn * 64 + (grp >> 1) * 8 + (lane & 7)) * STRIDE_H)
                                              + (grp & 1) * 8) * 2);

    float acc[4][8][4];
#pragma unroll
    for (int i = 0; i < 4; i++)
#pragma unroll
        for (int j = 0; j < 8; j++)
#pragma unroll
            for (int r = 0; r < 4; r++) acc[i][j][r] = 0.f;

    const int T = K / BK;

    // ---- prologue: stages 0,1
#pragma unroll
    for (int s = 0; s < 2; s++) {
        if (s < T) {
            const int kc = s * BK;
            const uint32_t so = (uint32_t)(s * TILE_BYTES_H);
#pragma unroll
            for (int i = 0; i < 4; i++) {
                uint32_t d = so + (uint32_t)((rowc[i] * STRIDE_H + koct) * 2);
                cp_async16(sAu + d, A  + (long)(m0 + rowc[i]) * K   + kc + koct);
                cp_async16(sBu + d, Bt + (long)(n0 + rowc[i]) * ldB + kc + koct);
            }
        }
        CP_COMMIT();
    }

    int cur = 0;
    for (int it = 0; it < T; it++) {
        CP_WAIT1();
        __syncthreads();

        if (it + 2 < T) {
            int ib = cur + 2; if (ib >= NSTAGE) ib -= NSTAGE;
            const int kc = (it + 2) * BK;
            const uint32_t so = (uint32_t)(ib * TILE_BYTES_H);
#pragma unroll
            for (int i = 0; i < 4; i++) {
                uint32_t d = so + (uint32_t)((rowc[i] * STRIDE_H + koct) * 2);
                cp_async16(sAu + d, A  + (long)(m0 + rowc[i]) * K   + kc + koct);
                cp_async16(sBu + d, Bt + (long)(n0 + rowc[i]) * ldB + kc + koct);
            }
        }
        CP_COMMIT();

        // ---- compute buffer cur: 2 k16-steps
        const uint32_t bufOff = (uint32_t)(cur * TILE_BYTES_H);
#pragma unroll
        for (int kt = 0; kt < 2; kt++) {
            const uint32_t kOff = bufOff + kt * 32;   // 16 halfs = 32B
            uint32_t a[4][4];
#pragma unroll
            for (int mi = 0; mi < 4; mi++)
                ldsm_x4(a[mi], aAddr0 + kOff + mi * (16 * STRIDE_H * 2));
            uint32_t b[4][4];   // [p] covers n-atoms 2p,2p+1: {b0,b1,b0',b1'}
#pragma unroll
            for (int p = 0; p < 4; p++)
                ldsm_x4(b[p], bAddr0 + kOff + p * (16 * STRIDE_H * 2));
#pragma unroll
            for (int mi = 0; mi < 4; mi++)
#pragma unroll
                for (int ni = 0; ni < 8; ni++)
                    mma_16x8x16(acc[mi][ni], a[mi], &b[ni >> 1][(ni & 1) * 2]);
        }

        if (++cur == NSTAGE) cur = 0;
    }

    // ---- epilogue
#pragma unroll
    for (int mi = 0; mi < 4; mi++) {
#pragma unroll
        for (int half = 0; half < 2; half++) {
            const long row = m0 + wm * 64 + mi * 16 + g + half * 8;
#pragma unroll
            for (int ni = 0; ni < 8; ni++) {
                const int col = n0 + wn * 64 + ni * 8 + 2 * tg;
                float rx = acc[mi][ni][half * 2 + 0] * alpha;
                float ry = acc[mi][ni][half * 2 + 1] * alpha;
                if (BIAS) {
                    float2 b2v = *reinterpret_cast<const float2*>(bias + col);
                    rx += b2v.x; ry += b2v.y;
                }
                if (RELU) { rx = fmaxf(rx, 0.f); ry = fmaxf(ry, 0.f); }
                if (OUT_HALF) {
                    __half* C16 = (__half*)Cv + (long)blockIdx.z * sC;
                    *reinterpret_cast<__half2*>(C16 + row * (long)N + col) =
                        __floats2half2_rn(rx, ry);
                } else {
                    float* C = (float*)Cv + (long)blockIdx.z * sC;
                    float2 r; r.x = rx; r.y = ry;
                    *reinterpret_cast<float2*>(C + row * (long)N + col) = r;
                }
            }
        }
    }
}

// ---------------------------------------------------------------------------
// fp32 -> fp16 elementwise convert (8 per thread)
// ---------------------------------------------------------------------------
__global__ __launch_bounds__(256)
void cvt_f2h(const float* __restrict__ in, __half* __restrict__ out, long n)
{
    long i = ((long)blockIdx.x * 256 + threadIdx.x) * 8;
    if (i >= n) return;
    float4 a = *reinterpret_cast<const float4*>(in + i);
    float4 b = *reinterpret_cast<const float4*>(in + i + 4);
    __half2* o = reinterpret_cast<__half2*>(out + i);
    o[0] = __floats2half2_rn(a.x, a.y);
    o[1] = __floats2half2_rn(a.z, a.w);
    o[2] = __floats2half2_rn(b.x, b.y);
    o[3] = __floats2half2_rn(b.z, b.w);
}

// ---------------------------------------------------------------------------
// 32x32 transposes: fp32 in -> fp16 out (weights), fp16 in -> fp16 out (vn)
// ---------------------------------------------------------------------------
__global__ __launch_bounds__(256)
void transpose_f2h(const float* __restrict__ in, __half* __restrict__ out, int R, int C)
{
    __shared__ float t[32][33];
    int c0 = blockIdx.x * 32, r0 = blockIdx.y * 32;
#pragma unroll
    for (int i = 0; i < 32; i += 8)
        t[threadIdx.y + i][threadIdx.x] = in[(long)(r0 + threadIdx.y + i) * C + c0 + threadIdx.x];
    __syncthreads();
#pragma unroll
    for (int i = 0; i < 32; i += 8)
        out[(long)(c0 + threadIdx.y + i) * R + r0 + threadIdx.x] =
            __float2half_rn(t[threadIdx.x][threadIdx.y + i]);
}

__global__ __launch_bounds__(256)
void transpose_h2h(const __half* __restrict__ in, __half* __restrict__ out, int R, int C)
{
    __shared__ float t[32][33];
    int c0 = blockIdx.x * 32, r0 = blockIdx.y * 32;
#pragma unroll
    for (int i = 0; i < 32; i += 8)
        t[threadIdx.y + i][threadIdx.x] =
            __half2float(in[(long)(r0 + threadIdx.y + i) * C + c0 + threadIdx.x]);
    __syncthreads();
#pragma unroll
    for (int i = 0; i < 32; i += 8)
        out[(long)(c0 + threadIdx.y + i) * R + r0 + threadIdx.x] =
            __float2half_rn(t[threadIdx.x][threadIdx.y + i]);
}

// ---------------------------------------------------------------------------
// LayerNorm D=512: fp32 in -> fp16 normalized out (+ optional raw fp32 residual)
// ---------------------------------------------------------------------------
__global__ __launch_bounds__(128)
void ln512_kernel(const float* __restrict__ X,
                  const float* __restrict__ gam, const float* __restrict__ bet,
                  __half* __restrict__ Y, float* __restrict__ res)
{
    long row = blockIdx.x;
    const int t = threadIdx.x;
    float4 v = reinterpret_cast<const float4*>(X + row * 512)[t];

    float s  = v.x + v.y + v.z + v.w;
    float sq = v.x * v.x + v.y * v.y + v.z * v.z + v.w * v.w;
#pragma unroll
    for (int o = 16; o > 0; o >>= 1) {
        s  += __shfl_xor_sync(0xffffffffu, s, o);
        sq += __shfl_xor_sync(0xffffffffu, sq, o);
    }
    __shared__ float sh_s[4], sh_q[4];
    int w = t >> 5, l = t & 31;
    if (l == 0) { sh_s[w] = s; sh_q[w] = sq; }
    __syncthreads();
    s  = sh_s[0] + sh_s[1] + sh_s[2] + sh_s[3];
    sq = sh_q[0] + sh_q[1] + sh_q[2] + sh_q[3];

    float mean = s * (1.f / 512.f);
    float var  = sq * (1.f / 512.f) - mean * mean;
    float rs   = rsqrtf(var + 1e-6f);

    if (res) reinterpret_cast<float4*>(res + row * 512)[t] = v;

    float4 g4 = reinterpret_cast<const float4*>(gam)[t];
    float4 b4 = reinterpret_cast<const float4*>(bet)[t];
    __half2* yo = reinterpret_cast<__half2*>(Y + row * 512) + 2 * t;
    yo[0] = __floats2half2_rn((v.x - mean) * rs * g4.x + b4.x,
                              (v.y - mean) * rs * g4.y + b4.y);
    yo[1] = __floats2half2_rn((v.z - mean) * rs * g4.z + b4.z,
                              (v.w - mean) * rs * g4.w + b4.w);
}

// ---------------------------------------------------------------------------
// Mask + softmax rows of 2048, in place (fp32, tf32-rounded output as R13)
// + fp16 operand copy for the attn@V GEMM.
// ---------------------------------------------------------------------------
__global__ __launch_bounds__(256)
void softmax2048_kernel(float* __restrict__ Scores, const int* __restrict__ mask,
                        __half* __restrict__ Sh)
{
    long row = blockIdx.x;
    float* s      = Scores + row * 2048;
    const int* m  = mask   + row * 2048;
    __half* sh16  = Sh     + row * 2048;
    const int t = threadIdx.x;

    float vals[8];
    float mx = -1e30f;
#pragma unroll
    for (int i = 0; i < 8; i++) {
        int c = t + i * 256;
        float x = s[c];
        if (m[c] == 0) x = -1e9f;
        vals[i] = x;
        mx = fmaxf(mx, x);
    }
    __shared__ float sh[8];
#pragma unroll
    for (int o = 16; o > 0; o >>= 1) mx = fmaxf(mx, __shfl_xor_sync(0xffffffffu, mx, o));
    int w = t >> 5, l = t & 31;
    if (l == 0) sh[w] = mx;
    __syncthreads();
    mx = sh[0];
#pragma unroll
    for (int i = 1; i < 8; i++) mx = fmaxf(mx, sh[i]);
    __syncthreads();

    float sum = 0.f;
#pragma unroll
    for (int i = 0; i < 8; i++) {
        vals[i] = __expf(vals[i] - mx);
        sum += vals[i];
    }
#pragma unroll
    for (int o = 16; o > 0; o >>= 1) sum += __shfl_xor_sync(0xffffffffu, sum, o);
    if (l == 0) sh[w] = sum;
    __syncthreads();
    sum = sh[0] + sh[1] + sh[2] + sh[3] + sh[4] + sh[5] + sh[6] + sh[7];

    float inv = 1.f / sum;
#pragma unroll
    for (int i = 0; i < 8; i++) {
        int c = t + i * 256;
        float p = vals[i] * inv;
        s[c]    = roundtf(p);
        sh16[c] = __float2half_rn(p);
    }
}

// ---------------------------------------------------------------------------
// Launch.  Order keeps ncu (-s 5 -c 1) on launch #5 = q-projection GEMM.
// ---------------------------------------------------------------------------
extern "C" void kernel_launch(void* const* d_in, const int* in_sizes, int n_in,
                              void* d_out_, int out_size)
{
    const float* q    = (const float*)d_in[0];
    const float* k    = (const float*)d_in[1];
    const float* v    = (const float*)d_in[2];
    const int*   mask = (const int*)  d_in[3];
    const float* Wq   = (const float*)d_in[4];
    const float* bq   = (const float*)d_in[5];
    const float* Wk   = (const float*)d_in[6];
    const float* bk   = (const float*)d_in[7];
    const float* Wv   = (const float*)d_in[8];
    const float* bv   = (const float*)d_in[9];
    const float* gq   = (const float*)d_in[10];
    const float* beq  = (const float*)d_in[11];
    const float* gk   = (const float*)d_in[12];
    const float* bek  = (const float*)d_in[13];
    const float* gv   = (const float*)d_in[14];
    const float* bev  = (const float*)d_in[15];
    const float* W1   = (const float*)d_in[16];
    const float* b1   = (const float*)d_in[17];
    const float* W2   = (const float*)d_in[18];
    const float* b2   = (const float*)d_in[19];
    float* out = (float*)d_out_;

    float  *qp, *kp, *vp;
    __half *qh, *kh, *vh, *qn, *kn, *vn, *vpT, *ath, *wqT, *wkT, *wvT, *w1T, *w2T;
    cudaGetSymbolAddress((void**)&qp,  g_qp);
    cudaGetSymbolAddress((void**)&kp,  g_kp);
    cudaGetSymbolAddress((void**)&vp,  g_vp);
    cudaGetSymbolAddress((void**)&qh,  g_qh);
    cudaGetSymbolAddress((void**)&kh,  g_kh);
    cudaGetSymbolAddress((void**)&vh,  g_vh);
    cudaGetSymbolAddress((void**)&qn,  g_qn);
    cudaGetSymbolAddress((void**)&kn,  g_kn);
    cudaGetSymbolAddress((void**)&vn,  g_vn);
    cudaGetSymbolAddress((void**)&vpT, g_vpT);
    cudaGetSymbolAddress((void**)&ath, g_ath);
    cudaGetSymbolAddress((void**)&wqT, g_wqT);
    cudaGetSymbolAddress((void**)&wkT, g_wkT);
    cudaGetSymbolAddress((void**)&wvT, g_wvT);
    cudaGetSymbolAddress((void**)&w1T, g_w1T);
    cudaGetSymbolAddress((void**)&w2T, g_w2T);
    __half* t1h = qn;   // qn dead after scores GEMM
    __half* t2h = kn;   // kn dead after scores GEMM

    cudaFuncSetAttribute(mma_gemm<true,  false, false>, cudaFuncAttributeMaxDynamicSharedMemorySize, SMEM_DYN);
    cudaFuncSetAttribute(mma_gemm<false, false, false>, cudaFuncAttributeMaxDynamicSharedMemorySize, SMEM_DYN);
    cudaFuncSetAttribute(mma_gemm<false, false, true >, cudaFuncAttributeMaxDynamicSharedMemorySize, SMEM_DYN);
    cudaFuncSetAttribute(mma_gemm<true,  true,  true >, cudaFuncAttributeMaxDynamicSharedMemorySize, SMEM_DYN);

    dim3 tb(32, 8);
    dim3 blk(128);
    const long NQKV = (long)NTc * DMc;
    const int  CVB  = (int)(NQKV / (256 * 8));

    // 0-2) QKV weight transposes (fp32 -> fp16)
    transpose_f2h<<<dim3(DKc/32,  DMc/32), tb>>>(Wq, wqT, DMc, DKc);   // #0
    transpose_f2h<<<dim3(DKc/32,  DMc/32), tb>>>(Wk, wkT, DMc, DKc);   // #1
    transpose_f2h<<<dim3(DVc/32,  DMc/32), tb>>>(Wv, wvT, DMc, DVc);   // #2

    // 3-4) convert q,k inputs to fp16
    cvt_f2h<<<CVB, 256>>>(q, qh, NQKV);                                // #3
    cvt_f2h<<<CVB, 256>>>(k, kh, NQKV);                                // #4

    // 5) q projection (+bias) -> fp32 qp
    mma_gemm<true, false, false><<<dim3(DKc/BN, NTc/BM, 1), blk, SMEM_DYN>>>(
        qh, wqT, bq, qp, NTc, DKc, DMc, DMc, 0, 0, 0, 1.f);            // #5 <- ncu

    // convert v; k,v projections
    cvt_f2h<<<CVB, 256>>>(v, vh, NQKV);
    mma_gemm<true, false, false><<<dim3(DKc/BN, NTc/BM, 1), blk, SMEM_DYN>>>(
        kh, wkT, bk, kp, NTc, DKc, DMc, DMc, 0, 0, 0, 1.f);
    mma_gemm<true, false, false><<<dim3(DVc/BN, NTc/BM, 1), blk, SMEM_DYN>>>(
        vh, wvT, bv, vp, NTc, DVc, DMc, DMc, 0, 0, 0, 1.f);

    // LayerNorm: fp32 in -> fp16 normalized out; q-LN also emits raw residual.
    ln512_kernel<<<NTc, 128>>>(qp, gq, beq, qn, out + OFF_RES);
    ln512_kernel<<<NTc, 128>>>(kp, gk, bek, kn, nullptr);
    ln512_kernel<<<NTc, 128>>>(vp, gv, bev, vn, nullptr);

    // vn^T (fp16) for the attn@V B-operand
    transpose_h2h<<<dim3(DVc/32, NTc/32), tb>>>(vn, vpT, NTc, DVc);

    // scores = (qn @ kn^T) / sqrt(dk) -> fp32 attn region
    mma_gemm<false, false, false><<<dim3(Sc/BN, Sc/BM, Bc), blk, SMEM_DYN>>>(
        qn, kn, nullptr, out + OFF_ATT, Sc, Sc, DKc, DKc,
        (long)Sc * DKc, (long)Sc * DKc, (long)Sc * Sc, INV_TEMP);

    // mask + softmax (tf32-rounded fp32 output, fp16 operand copy)
    softmax2048_kernel<<<NTc, 256>>>(out + OFF_ATT, mask, ath);

    // MLP weight transposes (fp32 -> fp16)
    transpose_f2h<<<dim3(DVc/32,  DVc/32), tb>>>(W1, w1T, DVc, DVc);
    transpose_f2h<<<dim3(DOUTc/32, DVc/32), tb>>>(W2, w2T, DVc, DOUTc);

    // out1 = attn @ vn -> fp16 t1h
    mma_gemm<false, false, true><<<dim3(DVc/BN, Sc/BM, Bc), blk, SMEM_DYN>>>(
        ath, vpT, nullptr, t1h, Sc, DVc, Sc, NTc,
        (long)Sc * Sc, (long)Sc, (long)Sc * DVc, 1.f);

    // h = relu(out1 @ W1 + b1) -> fp16 t2h
    mma_gemm<true, true, true><<<dim3(DVc/BN, NTc/BM, 1), blk, SMEM_DYN>>>(
        t1h, w1T, b1, t2h, NTc, DVc, DVc, DVc, 0, 0, 0, 1.f);

    // out = h @ W2 + b2 -> fp32 d_out
    mma_gemm<true, false, false><<<dim3(DOUTc/BN, NTc/BM, 1), blk, SMEM_DYN>>>(
        t2h, w2T, b2, out + OFF_OUT, NTc, DOUTc, DVc, DVc, 0, 0, 0, 1.f);
}